// round 8
// baseline (speedup 1.0000x reference)
#include <cuda_runtime.h>
#include <math.h>
#include <stdint.h>

// ---------------- problem constants ----------------
#define SQ   1024
#define HDM  2048
#define NHQ  32
#define NKVH 4
#define HDHD 128
#define NE   32
#define TOPK 8
#define IDIM 768
#define NPAIR (SQ*TOPK)   // 8192

// ---------------- device scratch ----------------
__device__ float g_h1[SQ*HDM];
__device__ float g_q [SQ*NHQ*HDHD];
__device__ float g_k [SQ*NKVH*HDHD];
__device__ float g_v [SQ*NKVH*HDHD];
__device__ float g_scores[(long long)NHQ*SQ*SQ];
__device__ float g_attn[SQ*NHQ*HDHD];
__device__ float g_h [SQ*HDM];
__device__ float g_h2[SQ*HDM];
__device__ float g_logits[SQ*NE];
__device__ float g_tw[NPAIR];
__device__ int   g_te[NPAIR];
__device__ int   g_counts[NE];
__device__ int   g_offsets[NE];
__device__ int   g_cursor[NE];
__device__ int   g_btok[NPAIR];
__device__ int   g_ppos[NPAIR];
__device__ float g_gu [(long long)NPAIR*2*IDIM];   // also reused as Wo split-K partials
__device__ float g_act[(long long)NPAIR*IDIM];
__device__ float g_ybuf[(long long)NPAIR*HDM];

// ---------------- helpers ----------------
__device__ __forceinline__ void cpasync16(void* dst, const void* src, int srcsize) {
    uint32_t d = (uint32_t)__cvta_generic_to_shared(dst);
    asm volatile("cp.async.cg.shared.global [%0], [%1], 16, %2;"
                 :: "r"(d), "l"(src), "r"(srcsize) : "memory");
}
__device__ __forceinline__ void cpasync_commit() {
    asm volatile("cp.async.commit_group;" ::: "memory");
}
// round-to-nearest-away into tf32's 19 kept bits (mma ignores low 13 bits)
__device__ __forceinline__ uint32_t rnd(float v) {
    return __float_as_uint(v) + 0x1000u;
}

// ---------------- small kernels ----------------
__global__ void zero32_kernel(int* counts, int* cursor) {
    int i = threadIdx.x;
    if (i < NE) { counts[i] = 0; cursor[i] = 0; }
}

__global__ void rmsnorm_kernel(const float* __restrict__ x, const float* __restrict__ w,
                               float* __restrict__ o, int ncols) {
    int row = blockIdx.x;
    const float* xr = x + (long long)row * ncols;
    float* orow = o + (long long)row * ncols;
    __shared__ float red[256];
    float s = 0.f;
    for (int c = threadIdx.x; c < ncols; c += 256) { float t = xr[c]; s += t * t; }
    red[threadIdx.x] = s; __syncthreads();
    for (int st = 128; st > 0; st >>= 1) {
        if (threadIdx.x < st) red[threadIdx.x] += red[threadIdx.x + st];
        __syncthreads();
    }
    float rms = rsqrtf(red[0] / (float)ncols + 1e-6f);
    for (int c = threadIdx.x; c < ncols; c += 256) orow[c] = xr[c] * rms * w[c];
}

__global__ void qknorm_rope_kernel(float* __restrict__ q, float* __restrict__ k,
                                   const float* __restrict__ qw, const float* __restrict__ kw) {
    int slot = blockIdx.x;
    int t    = blockIdx.y;
    float* vec; const float* w;
    if (slot < NHQ) { vec = q + (long long)t * (NHQ*HDHD) + slot * HDHD; w = qw; }
    else            { vec = k + (long long)t * (NKVH*HDHD) + (slot - NHQ) * HDHD; w = kw; }
    int d = threadIdx.x;
    float v = vec[d];
    float s = v * v;
    #pragma unroll
    for (int o = 16; o > 0; o >>= 1) s += __shfl_xor_sync(0xffffffffu, s, o);
    __shared__ float red[4];
    if ((d & 31) == 0) red[d >> 5] = s;
    __syncthreads();
    float tot = red[0] + red[1] + red[2] + red[3];
    float rms = rsqrtf(tot / 128.f + 1e-6f);
    float nv = v * rms * w[d];
    __shared__ float sv[128];
    sv[d] = nv;
    __syncthreads();
    int d2 = d & 63;
    float angle = (float)t * powf(10000.0f, -(float)(2 * d2) / 128.0f);
    float c = cosf(angle), sn = sinf(angle);
    float other = (d < 64) ? -sv[d + 64] : sv[d - 64];
    vec[d] = nv * c + other * sn;
}

__global__ void softmax_kernel(float* __restrict__ scores) {
    int i = blockIdx.x, h = blockIdx.y;
    float* row = scores + ((long long)h * SQ + i) * SQ;
    int len = i + 1;
    __shared__ float red[256];
    float m = -1e30f;
    for (int j = threadIdx.x; j < len; j += 256) m = fmaxf(m, row[j]);
    red[threadIdx.x] = m; __syncthreads();
    for (int st = 128; st > 0; st >>= 1) {
        if (threadIdx.x < st) red[threadIdx.x] = fmaxf(red[threadIdx.x], red[threadIdx.x + st]);
        __syncthreads();
    }
    m = red[0]; __syncthreads();
    float s = 0.f;
    for (int j = threadIdx.x; j < len; j += 256) { float e = __expf(row[j] - m); row[j] = e; s += e; }
    red[threadIdx.x] = s; __syncthreads();
    for (int st = 128; st > 0; st >>= 1) {
        if (threadIdx.x < st) red[threadIdx.x] += red[threadIdx.x + st];
        __syncthreads();
    }
    float inv = 1.f / red[0];
    int fill = ((i >> 7) + 1) << 7;   // AV K-loop trims at 128-block boundary
    for (int j = threadIdx.x; j < fill; j += 256) row[j] = (j < len) ? row[j] * inv : 0.f;
}

__global__ void topk_kernel(const float* __restrict__ logits, float* __restrict__ tw,
                            int* __restrict__ te) {
    int t = blockIdx.x * blockDim.x + threadIdx.x;
    if (t >= SQ) return;
    float p[NE];
    float m = -1e30f;
    for (int e = 0; e < NE; e++) { p[e] = logits[t * NE + e]; m = fmaxf(m, p[e]); }
    float s = 0.f;
    for (int e = 0; e < NE; e++) { p[e] = expf(p[e] - m); s += p[e]; }
    float inv = 1.f / s;
    bool used[NE];
    for (int e = 0; e < NE; e++) used[e] = false;
    for (int kk = 0; kk < TOPK; kk++) {
        int best = -1; float bv = -1e30f;
        for (int e = 0; e < NE; e++)
            if (!used[e] && p[e] > bv) { bv = p[e]; best = e; }
        used[best] = true;
        te[t * TOPK + kk] = best;
        tw[t * TOPK + kk] = p[best] * inv;
    }
}

__global__ void count_kernel(const int* __restrict__ te, int* __restrict__ counts) {
    int p = blockIdx.x * 256 + threadIdx.x;
    if (p < NPAIR) atomicAdd(&counts[te[p]], 1);
}

__global__ void scan_kernel(const int* __restrict__ counts, int* __restrict__ offsets) {
    if (threadIdx.x == 0) {
        int s = 0;
        for (int e = 0; e < NE; e++) { offsets[e] = s; s += counts[e]; }
    }
}

__global__ void assign_kernel(const int* __restrict__ te, const int* __restrict__ offsets,
                              int* __restrict__ cursor, int* __restrict__ btok,
                              int* __restrict__ ppos) {
    int p = blockIdx.x * 256 + threadIdx.x;
    if (p >= NPAIR) return;
    int e = te[p];
    int pos = offsets[e] + atomicAdd(&cursor[e], 1);
    btok[pos] = p >> 3;
    ppos[p] = pos;
}

__global__ void silu_kernel(const float* __restrict__ gu, float* __restrict__ act) {
    long long idx = (long long)blockIdx.x * 256 + threadIdx.x;
    if (idx >= (long long)NPAIR * IDIM) return;
    long long p = idx / IDIM, f = idx % IDIM;
    float g = gu[p * (2 * IDIM) + f];
    float u = gu[p * (2 * IDIM) + IDIM + f];
    act[idx] = (g / (1.f + __expf(-g))) * u;
}

// h = x + sum of 4 split-K partials (deterministic order)
__global__ void reduce4_kernel(const float* __restrict__ x, const float* __restrict__ part,
                               float* __restrict__ o) {
    int i = blockIdx.x * 256 + threadIdx.x;   // float4 index
    if (i >= SQ * HDM / 4) return;
    const float4* x4 = (const float4*)x;
    const float4* p4 = (const float4*)part;
    float4 a = x4[i];
    #pragma unroll
    for (int z = 0; z < 4; z++) {
        float4 b = p4[(long long)z * (SQ * HDM / 4) + i];
        a.x += b.x; a.y += b.y; a.z += b.z; a.w += b.w;
    }
    ((float4*)o)[i] = a;
}

__global__ void combine_kernel(const float* __restrict__ h, const float* __restrict__ ybuf,
                               const int* __restrict__ ppos, const float* __restrict__ tw,
                               float* __restrict__ out) {
    int t = blockIdx.x;
    __shared__ int   pos[TOPK];
    __shared__ float ww[TOPK];
    if (threadIdx.x < TOPK) {
        pos[threadIdx.x] = ppos[t * TOPK + threadIdx.x];
        ww[threadIdx.x]  = tw[t * TOPK + threadIdx.x];
    }
    __syncthreads();
    const float4* h4 = (const float4*)(h + (long long)t * HDM);
    float4* o4 = (float4*)(out + (long long)t * HDM);
    for (int c = threadIdx.x; c < HDM / 4; c += 256) {
        float4 a = h4[c];
        #pragma unroll
        for (int kk = 0; kk < TOPK; kk++) {
            float4 b = ((const float4*)(ybuf + (long long)pos[kk] * HDM))[c];
            float wv = ww[kk];
            a.x += wv * b.x; a.y += wv * b.y; a.z += wv * b.z; a.w += wv * b.w;
        }
        o4[c] = a;
    }
}

// ---------------- exact fp32 SIMT GEMM (gate logits only) ----------------
__global__ void gemm_simt_kernel(const float* __restrict__ A, const float* __restrict__ B,
                                 float* __restrict__ C, int M, int N, int K,
                                 int lda, int ldb, int ldc) {
    __shared__ float As[16][64 + 4];
    __shared__ float Bs[16][64];
    int tid = threadIdx.x;
    int tx = tid & 15, ty = tid >> 4;
    int row0 = blockIdx.y * 64;
    int col0 = blockIdx.x * 64;
    float acc[4][4] = {};
    for (int k0 = 0; k0 < K; k0 += 16) {
        for (int i = tid; i < 64 * 16; i += 256) {
            int m = i >> 4, kk = i & 15;
            int gr = row0 + m;
            As[kk][m] = (gr < M) ? A[(long long)gr * lda + k0 + kk] : 0.f;
        }
        for (int i = tid; i < 16 * 64; i += 256) {
            int kk = i >> 6, n = i & 63;
            int gc = col0 + n;
            Bs[kk][n] = (gc < N) ? B[(long long)(k0 + kk) * ldb + gc] : 0.f;
        }
        __syncthreads();
        #pragma unroll
        for (int kk = 0; kk < 16; kk++) {
            float a[4], b[4];
            #pragma unroll
            for (int i = 0; i < 4; i++) a[i] = As[kk][ty * 4 + i];
            #pragma unroll
            for (int j = 0; j < 4; j++) b[j] = Bs[kk][tx * 4 + j];
            #pragma unroll
            for (int i = 0; i < 4; i++)
                #pragma unroll
                for (int j = 0; j < 4; j++)
                    acc[i][j] += a[i] * b[j];
        }
        __syncthreads();
    }
    #pragma unroll
    for (int i = 0; i < 4; i++) {
        int r = row0 + ty * 4 + i;
        if (r >= M) continue;
        #pragma unroll
        for (int j = 0; j < 4; j++) {
            int c = col0 + tx * 4 + j;
            if (c < N) C[(long long)r * ldc + c] = acc[i][j];
        }
    }
}

// ---------------- tf32 tensor-core GEMM, BK=32, 2-stage cp.async, 3 CTAs/SM ----------------
// modes: 0 = batched; 1 = gathered rows via btok; 2 = contiguous rows from offsets;
//        3 = fused QKV (B/C = Wq/q, B2/C2 = Wk/k, B3/C3 = Wv/v)
#define BK 32
#define ASTRIDE 36
#define ASZ (128*ASTRIDE)                 // floats per A stage
template<int TRANSB>
__global__ void __launch_bounds__(256, 3)
gemm_tc(const float* __restrict__ A, const float* __restrict__ B, float* __restrict__ C,
        const float* __restrict__ resid,
        int M, int K, int lda, int ldb, int ldc,
        long long sA, long long sB, long long sC, int bDivB,
        int causal, int trimK, float alpha, int mode,
        const int* __restrict__ counts, const int* __restrict__ offsets,
        const int* __restrict__ btok,
        const float* __restrict__ B2, float* __restrict__ C2,
        const float* __restrict__ B3, float* __restrict__ C3) {
    constexpr int BM = 128, BN = 128;
    constexpr int WM = 64, WN = 32;
    constexpr int FM = 4, FN = 4;
    constexpr int BSZ = TRANSB ? (BN * ASTRIDE) : (BK * (BN + 8));

    extern __shared__ float smem[];
    float* sA_ = smem;                 // 2 stages of A
    float* sB_ = smem + 2 * ASZ;       // 2 stages of B
    __shared__ int stok[BM];

    int z = blockIdx.z;
    int tid = threadIdx.x;
    int row0 = blockIdx.y * BM;
    int col0 = blockIdx.x * BN;

    const float* Az = A;
    const float* Bz;
    float* Cz;
    if (mode == 0) {
        Az = A + (long long)z * sA;
        Bz = B + (long long)(z / bDivB) * sB;
        Cz = C + (long long)z * sC;
    } else if (mode == 3) {
        if (z < 32)      { Bz = B;  Cz = C;  ldb = ldc = NHQ*HDHD;  col0 = z * BN; }
        else if (z < 36) { Bz = B2; Cz = C2; ldb = ldc = NKVH*HDHD; col0 = (z - 32) * BN; }
        else             { Bz = B3; Cz = C3; ldb = ldc = NKVH*HDHD; col0 = (z - 36) * BN; }
    } else {
        Bz = B + (long long)z * sB;
        Cz = C;
    }

    int cnt = M, start = 0;
    if (mode == 1 || mode == 2) { cnt = counts[z]; start = offsets[z]; }
    if ((mode == 1 || mode == 2) && row0 >= cnt) return;
    if (causal && col0 > row0) return;

    if (mode == 1) {
        for (int i = tid; i < BM; i += 256)
            stok[i] = (row0 + i < cnt) ? btok[start + row0 + i] : 0;
        __syncthreads();
    }

    int warp = tid >> 5, lane = tid & 31;
    int wr = (warp >> 2) * WM, wc = (warp & 3) * WN;
    int g = lane >> 2, t = lane & 3;

    float acc[FM][FN][4];
    #pragma unroll
    for (int i = 0; i < FM; i++)
        #pragma unroll
        for (int j = 0; j < FN; j++)
            #pragma unroll
            for (int r = 0; r < 4; r++) acc[i][j][r] = 0.f;

    auto loadTiles = [&](int st, int k0) {
        float* a = sA_ + st * ASZ;
        float* b = sB_ + st * BSZ;
        #pragma unroll
        for (int i = tid; i < BM * 8; i += 256) {
            int r = i >> 3, kq = i & 7;
            bool val = (row0 + r < cnt);
            long long ar = 0;
            if (val) {
                if (mode == 1)      ar = stok[r];
                else if (mode == 2) ar = start + row0 + r;
                else                ar = row0 + r;
            }
            cpasync16(a + r * ASTRIDE + kq * 4, Az + ar * lda + k0 + kq * 4, val ? 16 : 0);
        }
        if (!TRANSB) {
            #pragma unroll
            for (int i = tid; i < BK * (BN / 4); i += 256) {
                int kk = i >> 5, nq = i & 31;
                cpasync16(b + kk * (BN + 8) + nq * 4,
                          Bz + (long long)(k0 + kk) * ldb + col0 + nq * 4, 16);
            }
        } else {
            #pragma unroll
            for (int i = tid; i < BN * 8; i += 256) {
                int n = i >> 3, kq = i & 7;
                cpasync16(b + n * ASTRIDE + kq * 4,
                          Bz + (long long)(col0 + n) * ldb + k0 + kq * 4, 16);
            }
        }
    };

    auto compute = [&](int st) {
        const float* a_ = sA_ + st * ASZ;
        const float* b_ = sB_ + st * BSZ;
        #pragma unroll
        for (int ks = 0; ks < 4; ks++) {
            int kb = ks * 8;
            uint32_t a[FM][4], b[FN][2];
            #pragma unroll
            for (int fm = 0; fm < FM; fm++) {
                int m0 = wr + fm * 16;
                a[fm][0] = rnd(a_[(m0 + g) * ASTRIDE + kb + t]);
                a[fm][1] = rnd(a_[(m0 + g + 8) * ASTRIDE + kb + t]);
                a[fm][2] = rnd(a_[(m0 + g) * ASTRIDE + kb + t + 4]);
                a[fm][3] = rnd(a_[(m0 + g + 8) * ASTRIDE + kb + t + 4]);
            }
            #pragma unroll
            for (int fn = 0; fn < FN; fn++) {
                int n0 = wc + fn * 8 + g;
                if (TRANSB) {
                    b[fn][0] = rnd(b_[n0 * ASTRIDE + kb + t]);
                    b[fn][1] = rnd(b_[n0 * ASTRIDE + kb + t + 4]);
                } else {
                    b[fn][0] = rnd(b_[(kb + t) * (BN + 8) + n0]);
                    b[fn][1] = rnd(b_[(kb + t + 4) * (BN + 8) + n0]);
                }
            }
            #pragma unroll
            for (int fm = 0; fm < FM; fm++)
                #pragma unroll
                for (int fn = 0; fn < FN; fn++) {
                    asm volatile(
                        "mma.sync.aligned.m16n8k8.row.col.f32.tf32.tf32.f32 "
                        "{%0,%1,%2,%3}, {%4,%5,%6,%7}, {%8,%9}, {%0,%1,%2,%3};"
                        : "+f"(acc[fm][fn][0]), "+f"(acc[fm][fn][1]),
                          "+f"(acc[fm][fn][2]), "+f"(acc[fm][fn][3])
                        : "r"(a[fm][0]), "r"(a[fm][1]), "r"(a[fm][2]), "r"(a[fm][3]),
                          "r"(b[fn][0]), "r"(b[fn][1]));
                }
        }
    };

    int kLimit = trimK ? (row0 + BM < K ? row0 + BM : K) : K;
    int nk = kLimit / BK;

    loadTiles(0, 0);
    cpasync_commit();
    for (int ks = 0; ks < nk; ks++) {
        if (ks + 1 < nk) {
            loadTiles((ks + 1) & 1, (ks + 1) * BK);
            cpasync_commit();
            asm volatile("cp.async.wait_group 1;" ::: "memory");
        } else {
            asm volatile("cp.async.wait_group 0;" ::: "memory");
        }
        __syncthreads();
        compute(ks & 1);
        __syncthreads();
    }

    // ---- epilogue ----
    #pragma unroll
    for (int fm = 0; fm < FM; fm++) {
        #pragma unroll
        for (int rr = 0; rr < 2; rr++) {
            int lr = wr + fm * 16 + g + rr * 8;
            if (row0 + lr >= cnt) continue;
            long long crow = (mode == 1 || mode == 2) ? (long long)(start + row0 + lr)
                                                      : (long long)(row0 + lr);
            float* cp = Cz + crow * ldc;
            const float* rp = resid ? (resid + (long long)(row0 + lr) * ldc) : nullptr;
            #pragma unroll
            for (int fn = 0; fn < FN; fn++) {
                int c = col0 + wc + fn * 8 + t * 2;
                float v0 = alpha * acc[fm][fn][rr * 2 + 0];
                float v1 = alpha * acc[fm][fn][rr * 2 + 1];
                if (rp) { v0 += rp[c]; v1 += rp[c + 1]; }
                cp[c] = v0;
                cp[c + 1] = v1;
            }
        }
    }
}

// ---------------- host launcher ----------------
static void* symaddr(const void* s) { void* p = nullptr; cudaGetSymbolAddress(&p, s); return p; }

extern "C" void kernel_launch(void* const* d_in, const int* in_sizes, int n_in,
                              void* d_out, int out_size) {
    const float* x   = (const float*)d_in[0];
    const float* ln1 = (const float*)d_in[1];
    const float* ln2 = (const float*)d_in[2];
    const float* qnw = (const float*)d_in[3];
    const float* knw = (const float*)d_in[4];
    const float* Wq  = (const float*)d_in[5];
    const float* Wk  = (const float*)d_in[6];
    const float* Wv  = (const float*)d_in[7];
    const float* Wo  = (const float*)d_in[8];
    const float* Wg  = (const float*)d_in[9];
    const float* Wgu = (const float*)d_in[10];
    const float* Wd  = (const float*)d_in[11];
    float* out = (float*)d_out;

    float* h1   = (float*)symaddr(g_h1);
    float* q    = (float*)symaddr(g_q);
    float* k    = (float*)symaddr(g_k);
    float* v    = (float*)symaddr(g_v);
    float* sc   = (float*)symaddr(g_scores);
    float* attn = (float*)symaddr(g_attn);
    float* h    = (float*)symaddr(g_h);
    float* h2   = (float*)symaddr(g_h2);
    float* lg   = (float*)symaddr(g_logits);
    float* tw   = (float*)symaddr(g_tw);
    int*   te   = (int*)symaddr(g_te);
    int*   cnts = (int*)symaddr(g_counts);
    int*   offs = (int*)symaddr(g_offsets);
    int*   cur  = (int*)symaddr(g_cursor);
    int*   btok = (int*)symaddr(g_btok);
    int*   ppos = (int*)symaddr(g_ppos);
    float* gu   = (float*)symaddr(g_gu);
    float* act  = (float*)symaddr(g_act);
    float* ybuf = (float*)symaddr(g_ybuf);

    const float scale = 0.08838834764831843f;   // 1/sqrt(128)

    const size_t smem0 = (size_t)(2 * ASZ + 2 * (BK * (128 + 8))) * 4;   // non-trans: 71680
    const size_t smem1 = (size_t)(2 * ASZ + 2 * (128 * ASTRIDE)) * 4;    // trans:     73728
    static int attrDone = 0;
    if (!attrDone) {
        cudaFuncSetAttribute((const void*)gemm_tc<0>,
                             cudaFuncAttributeMaxDynamicSharedMemorySize, 80 * 1024);
        cudaFuncSetAttribute((const void*)gemm_tc<1>,
                             cudaFuncAttributeMaxDynamicSharedMemorySize, 80 * 1024);
        attrDone = 1;
    }

    zero32_kernel<<<1, 32>>>(cnts, cur);

    // ---- attention ----
    rmsnorm_kernel<<<SQ, 256>>>(x, ln1, h1, HDM);

    // fused QKV projection
    gemm_tc<0><<<dim3(1, 8, 40), 256, smem0>>>(h1, Wq, q, nullptr,
        SQ, HDM, HDM, 0, 0, 0, 0, 0, 1, 0, 0, 1.f, 3,
        nullptr, nullptr, nullptr, Wk, k, Wv, v);

    qknorm_rope_kernel<<<dim3(NHQ + NKVH, SQ), 128>>>(q, k, qnw, knw);

    // scores = q @ k^T (causal skip)
    gemm_tc<1><<<dim3(8, 8, NHQ), 256, smem1>>>(q, k, sc, nullptr,
        SQ, HDHD, NHQ*HDHD, NKVH*HDHD, SQ,
        HDHD, HDHD, (long long)SQ*SQ, 8, 1, 0, scale, 0,
        nullptr, nullptr, nullptr, nullptr, nullptr, nullptr, nullptr);

    softmax_kernel<<<dim3(SQ, NHQ), 256>>>(sc);

    // attn = probs @ v (K trimmed at diagonal)
    gemm_tc<0><<<dim3(1, 8, NHQ), 256, smem0>>>(sc, v, attn, nullptr,
        SQ, SQ, SQ, NKVH*HDHD, NHQ*HDHD,
        (long long)SQ*SQ, HDHD, HDHD, 8, 0, 1, 1.f, 0,
        nullptr, nullptr, nullptr, nullptr, nullptr, nullptr, nullptr);

    // Wo projection, split-K=4 (grid 128 -> 512 blocks), partials in gu scratch
    gemm_tc<0><<<dim3(16, 8, 4), 256, smem0>>>(attn, Wo, gu, nullptr,
        SQ, NHQ*HDHD/4, NHQ*HDHD, HDM, HDM,
        (long long)(NHQ*HDHD/4), (long long)(NHQ*HDHD/4)*HDM, (long long)SQ*HDM, 1,
        0, 0, 1.f, 0,
        nullptr, nullptr, nullptr, nullptr, nullptr, nullptr, nullptr);
    // h = x + sum of partials
    reduce4_kernel<<<(SQ*HDM/4 + 255)/256, 256>>>(x, gu, h);

    // ---- MoE ----
    rmsnorm_kernel<<<SQ, 256>>>(h, ln2, h2, HDM);

    gemm_simt_kernel<<<dim3(1, 16, 1), 256>>>(h2, Wg, lg, SQ, NE, HDM, HDM, NE, NE);
    topk_kernel<<<4, 256>>>(lg, tw, te);
    count_kernel<<<(NPAIR + 255) / 256, 256>>>(te, cnts);
    scan_kernel<<<1, 32>>>(cnts, offs);
    assign_kernel<<<(NPAIR + 255) / 256, 256>>>(te, offs, cur, btok, ppos);

    gemm_tc<0><<<dim3(2*IDIM/128, 8, NE), 256, smem0>>>(h2, Wgu, gu, nullptr,
        SQ, HDM, HDM, 2*IDIM, 2*IDIM,
        0, (long long)HDM*2*IDIM, 0, 1, 0, 0, 1.f, 1,
        cnts, offs, btok, nullptr, nullptr, nullptr, nullptr);

    silu_kernel<<<(int)(((long long)NPAIR*IDIM + 255) / 256), 256>>>(gu, act);

    gemm_tc<0><<<dim3(HDM/128, 8, NE), 256, smem0>>>(act, Wd, ybuf, nullptr,
        SQ, IDIM, IDIM, HDM, HDM,
        0, (long long)IDIM*HDM, 0, 1, 0, 0, 1.f, 2,
        cnts, offs, nullptr, nullptr, nullptr, nullptr, nullptr);

    combine_kernel<<<SQ, 256>>>(h, ybuf, ppos, tw, out);
}

// round 9
// speedup vs baseline: 1.2709x; 1.2709x over previous
#include <cuda_runtime.h>
#include <math.h>
#include <stdint.h>

// ---------------- problem constants ----------------
#define SQ   1024
#define HDM  2048
#define NHQ  32
#define NKVH 4
#define HDHD 128
#define NE   32
#define TOPK 8
#define IDIM 768
#define NPAIR (SQ*TOPK)   // 8192

// ---------------- device scratch ----------------
__device__ float g_h1[SQ*HDM];
__device__ float g_q [SQ*NHQ*HDHD];
__device__ float g_k [SQ*NKVH*HDHD];
__device__ float g_v [SQ*NKVH*HDHD];
__device__ float g_scores[(long long)NHQ*SQ*SQ];
__device__ float g_attn[SQ*NHQ*HDHD];
__device__ float g_h [SQ*HDM];
__device__ float g_h2[SQ*HDM];
__device__ float g_logits[SQ*NE];
__device__ float g_tw[NPAIR];
__device__ int   g_te[NPAIR];
__device__ int   g_counts[NE];
__device__ int   g_offsets[NE];
__device__ int   g_cursor[NE];
__device__ int   g_btok[NPAIR];
__device__ int   g_ppos[NPAIR];
__device__ float g_gu [(long long)NPAIR*2*IDIM];
__device__ float g_act[(long long)NPAIR*IDIM];
__device__ float g_ybuf[(long long)NPAIR*HDM];

// ---------------- helpers ----------------
__device__ __forceinline__ void cpasync16(void* dst, const void* src, int srcsize) {
    uint32_t d = (uint32_t)__cvta_generic_to_shared(dst);
    asm volatile("cp.async.cg.shared.global [%0], [%1], 16, %2;"
                 :: "r"(d), "l"(src), "r"(srcsize) : "memory");
}
__device__ __forceinline__ void cpasync_commit() {
    asm volatile("cp.async.commit_group;" ::: "memory");
}
// round-to-nearest-away into tf32's 19 kept bits (mma ignores low 13 bits)
__device__ __forceinline__ uint32_t rnd(float v) {
    return __float_as_uint(v) + 0x1000u;
}

// ---------------- small kernels ----------------
__global__ void zero32_kernel(int* counts, int* cursor) {
    int i = threadIdx.x;
    if (i < NE) { counts[i] = 0; cursor[i] = 0; }
}

__global__ void rmsnorm_kernel(const float* __restrict__ x, const float* __restrict__ w,
                               float* __restrict__ o, int ncols) {
    int row = blockIdx.x;
    const float* xr = x + (long long)row * ncols;
    float* orow = o + (long long)row * ncols;
    __shared__ float red[256];
    float s = 0.f;
    for (int c = threadIdx.x; c < ncols; c += 256) { float t = xr[c]; s += t * t; }
    red[threadIdx.x] = s; __syncthreads();
    for (int st = 128; st > 0; st >>= 1) {
        if (threadIdx.x < st) red[threadIdx.x] += red[threadIdx.x + st];
        __syncthreads();
    }
    float rms = rsqrtf(red[0] / (float)ncols + 1e-6f);
    for (int c = threadIdx.x; c < ncols; c += 256) orow[c] = xr[c] * rms * w[c];
}

__global__ void qknorm_rope_kernel(float* __restrict__ q, float* __restrict__ k,
                                   const float* __restrict__ qw, const float* __restrict__ kw) {
    int slot = blockIdx.x;
    int t    = blockIdx.y;
    float* vec; const float* w;
    if (slot < NHQ) { vec = q + (long long)t * (NHQ*HDHD) + slot * HDHD; w = qw; }
    else            { vec = k + (long long)t * (NKVH*HDHD) + (slot - NHQ) * HDHD; w = kw; }
    int d = threadIdx.x;
    float v = vec[d];
    float s = v * v;
    #pragma unroll
    for (int o = 16; o > 0; o >>= 1) s += __shfl_xor_sync(0xffffffffu, s, o);
    __shared__ float red[4];
    if ((d & 31) == 0) red[d >> 5] = s;
    __syncthreads();
    float tot = red[0] + red[1] + red[2] + red[3];
    float rms = rsqrtf(tot / 128.f + 1e-6f);
    float nv = v * rms * w[d];
    __shared__ float sv[128];
    sv[d] = nv;
    __syncthreads();
    int d2 = d & 63;
    float angle = (float)t * powf(10000.0f, -(float)(2 * d2) / 128.0f);
    float c = cosf(angle), sn = sinf(angle);
    float other = (d < 64) ? -sv[d + 64] : sv[d - 64];
    vec[d] = nv * c + other * sn;
}

__global__ void softmax_kernel(float* __restrict__ scores) {
    int i = blockIdx.x, h = blockIdx.y;
    float* row = scores + ((long long)h * SQ + i) * SQ;
    int len = i + 1;
    __shared__ float red[256];
    float m = -1e30f;
    for (int j = threadIdx.x; j < len; j += 256) m = fmaxf(m, row[j]);
    red[threadIdx.x] = m; __syncthreads();
    for (int st = 128; st > 0; st >>= 1) {
        if (threadIdx.x < st) red[threadIdx.x] = fmaxf(red[threadIdx.x], red[threadIdx.x + st]);
        __syncthreads();
    }
    m = red[0]; __syncthreads();
    float s = 0.f;
    for (int j = threadIdx.x; j < len; j += 256) { float e = __expf(row[j] - m); row[j] = e; s += e; }
    red[threadIdx.x] = s; __syncthreads();
    for (int st = 128; st > 0; st >>= 1) {
        if (threadIdx.x < st) red[threadIdx.x] += red[threadIdx.x + st];
        __syncthreads();
    }
    float inv = 1.f / red[0];
    int fill = ((i >> 7) + 1) << 7;   // AV K-loop trims at 128-block boundary
    for (int j = threadIdx.x; j < fill; j += 256) row[j] = (j < len) ? row[j] * inv : 0.f;
}

__global__ void topk_kernel(const float* __restrict__ logits, float* __restrict__ tw,
                            int* __restrict__ te) {
    int t = blockIdx.x * blockDim.x + threadIdx.x;
    if (t >= SQ) return;
    float p[NE];
    float m = -1e30f;
    for (int e = 0; e < NE; e++) { p[e] = logits[t * NE + e]; m = fmaxf(m, p[e]); }
    float s = 0.f;
    for (int e = 0; e < NE; e++) { p[e] = expf(p[e] - m); s += p[e]; }
    float inv = 1.f / s;
    bool used[NE];
    for (int e = 0; e < NE; e++) used[e] = false;
    for (int kk = 0; kk < TOPK; kk++) {
        int best = -1; float bv = -1e30f;
        for (int e = 0; e < NE; e++)
            if (!used[e] && p[e] > bv) { bv = p[e]; best = e; }
        used[best] = true;
        te[t * TOPK + kk] = best;
        tw[t * TOPK + kk] = p[best] * inv;
    }
}

__global__ void count_kernel(const int* __restrict__ te, int* __restrict__ counts) {
    int p = blockIdx.x * 256 + threadIdx.x;
    if (p < NPAIR) atomicAdd(&counts[te[p]], 1);
}

__global__ void scan_kernel(const int* __restrict__ counts, int* __restrict__ offsets) {
    if (threadIdx.x == 0) {
        int s = 0;
        for (int e = 0; e < NE; e++) { offsets[e] = s; s += counts[e]; }
    }
}

__global__ void assign_kernel(const int* __restrict__ te, const int* __restrict__ offsets,
                              int* __restrict__ cursor, int* __restrict__ btok,
                              int* __restrict__ ppos) {
    int p = blockIdx.x * 256 + threadIdx.x;
    if (p >= NPAIR) return;
    int e = te[p];
    int pos = offsets[e] + atomicAdd(&cursor[e], 1);
    btok[pos] = p >> 3;
    ppos[p] = pos;
}

__global__ void silu_kernel(const float* __restrict__ gu, float* __restrict__ act) {
    long long idx = (long long)blockIdx.x * 256 + threadIdx.x;
    if (idx >= (long long)NPAIR * IDIM) return;
    long long p = idx / IDIM, f = idx % IDIM;
    float g = gu[p * (2 * IDIM) + f];
    float u = gu[p * (2 * IDIM) + IDIM + f];
    act[idx] = (g / (1.f + __expf(-g))) * u;
}

__global__ void combine_kernel(const float* __restrict__ h, const float* __restrict__ ybuf,
                               const int* __restrict__ ppos, const float* __restrict__ tw,
                               float* __restrict__ out) {
    int t = blockIdx.x;
    __shared__ int   pos[TOPK];
    __shared__ float ww[TOPK];
    if (threadIdx.x < TOPK) {
        pos[threadIdx.x] = ppos[t * TOPK + threadIdx.x];
        ww[threadIdx.x]  = tw[t * TOPK + threadIdx.x];
    }
    __syncthreads();
    const float4* h4 = (const float4*)(h + (long long)t * HDM);
    float4* o4 = (float4*)(out + (long long)t * HDM);
    for (int c = threadIdx.x; c < HDM / 4; c += 256) {
        float4 a = h4[c];
        #pragma unroll
        for (int kk = 0; kk < TOPK; kk++) {
            float4 b = ((const float4*)(ybuf + (long long)pos[kk] * HDM))[c];
            float wv = ww[kk];
            a.x += wv * b.x; a.y += wv * b.y; a.z += wv * b.z; a.w += wv * b.w;
        }
        o4[c] = a;
    }
}

// ---------------- exact fp32 SIMT GEMM (gate logits only) ----------------
__global__ void gemm_simt_kernel(const float* __restrict__ A, const float* __restrict__ B,
                                 float* __restrict__ C, int M, int N, int K,
                                 int lda, int ldb, int ldc) {
    __shared__ float As[16][64 + 4];
    __shared__ float Bs[16][64];
    int tid = threadIdx.x;
    int tx = tid & 15, ty = tid >> 4;
    int row0 = blockIdx.y * 64;
    int col0 = blockIdx.x * 64;
    float acc[4][4] = {};
    for (int k0 = 0; k0 < K; k0 += 16) {
        for (int i = tid; i < 64 * 16; i += 256) {
            int m = i >> 4, kk = i & 15;
            int gr = row0 + m;
            As[kk][m] = (gr < M) ? A[(long long)gr * lda + k0 + kk] : 0.f;
        }
        for (int i = tid; i < 16 * 64; i += 256) {
            int kk = i >> 6, n = i & 63;
            int gc = col0 + n;
            Bs[kk][n] = (gc < N) ? B[(long long)(k0 + kk) * ldb + gc] : 0.f;
        }
        __syncthreads();
        #pragma unroll
        for (int kk = 0; kk < 16; kk++) {
            float a[4], b[4];
            #pragma unroll
            for (int i = 0; i < 4; i++) a[i] = As[kk][ty * 4 + i];
            #pragma unroll
            for (int j = 0; j < 4; j++) b[j] = Bs[kk][tx * 4 + j];
            #pragma unroll
            for (int i = 0; i < 4; i++)
                #pragma unroll
                for (int j = 0; j < 4; j++)
                    acc[i][j] += a[i] * b[j];
        }
        __syncthreads();
    }
    #pragma unroll
    for (int i = 0; i < 4; i++) {
        int r = row0 + ty * 4 + i;
        if (r >= M) continue;
        #pragma unroll
        for (int j = 0; j < 4; j++) {
            int c = col0 + tx * 4 + j;
            if (c < N) C[(long long)r * ldc + c] = acc[i][j];
        }
    }
}

// ---------------- tf32 tensor-core GEMM, BK=32, 3-stage cp.async ----------------
// templated on BM (128: 256 thr / 256: 512 thr) and TRANSB.
// modes: 0 = batched; 1 = gathered rows via btok; 2 = contiguous rows from offsets;
//        3 = fused QKV (B/C = Wq/q, B2/C2 = Wk/k, B3/C3 = Wv/v)
#define BK 32
#define ASTRIDE 36
template<int BM, int TRANSB>
__global__ void __launch_bounds__(BM*2, 1)
gemm_tc(const float* __restrict__ A, const float* __restrict__ B, float* __restrict__ C,
        const float* __restrict__ resid,
        int M, int K, int lda, int ldb, int ldc,
        long long sA, long long sB, long long sC, int bDivB,
        int causal, int trimK, float alpha, int mode,
        const int* __restrict__ counts, const int* __restrict__ offsets,
        const int* __restrict__ btok,
        const float* __restrict__ B2, float* __restrict__ C2,
        const float* __restrict__ B3, float* __restrict__ C3) {
    constexpr int BN = 128;
    constexpr int THREADS = BM * 2;
    constexpr int FM = 4, FN = 4;
    constexpr int ASZ = BM * ASTRIDE;                       // floats per A stage
    constexpr int BSZ = TRANSB ? (BN * ASTRIDE) : (BK * (BN + 8));

    extern __shared__ float smem[];
    float* sA_ = smem;                 // 3 stages of A
    float* sB_ = smem + 3 * ASZ;       // 3 stages of B
    __shared__ int stok[BM];

    int z = blockIdx.z;
    int tid = threadIdx.x;
    int row0 = blockIdx.y * BM;
    int col0 = blockIdx.x * BN;

    const float* Az = A;
    const float* Bz;
    float* Cz;
    if (mode == 0) {
        Az = A + (long long)z * sA;
        Bz = B + (long long)(z / bDivB) * sB;
        Cz = C + (long long)z * sC;
    } else if (mode == 3) {
        if (z < 32)      { Bz = B;  Cz = C;  ldb = ldc = NHQ*HDHD;  col0 = z * BN; }
        else if (z < 36) { Bz = B2; Cz = C2; ldb = ldc = NKVH*HDHD; col0 = (z - 32) * BN; }
        else             { Bz = B3; Cz = C3; ldb = ldc = NKVH*HDHD; col0 = (z - 36) * BN; }
    } else {
        Bz = B + (long long)z * sB;
        Cz = C;
    }

    int cnt = M, start = 0;
    if (mode == 1 || mode == 2) { cnt = counts[z]; start = offsets[z]; }
    if ((mode == 1 || mode == 2) && row0 >= cnt) return;
    if (causal && col0 > row0) return;

    if (mode == 1) {
        for (int i = tid; i < BM; i += THREADS)
            stok[i] = (row0 + i < cnt) ? btok[start + row0 + i] : 0;
        __syncthreads();
    }

    int warp = tid >> 5, lane = tid & 31;
    int wr = (warp >> 2) * 64, wc = (warp & 3) * 32;
    int g = lane >> 2, t = lane & 3;

    float acc[FM][FN][4];
    #pragma unroll
    for (int i = 0; i < FM; i++)
        #pragma unroll
        for (int j = 0; j < FN; j++)
            #pragma unroll
            for (int r = 0; r < 4; r++) acc[i][j][r] = 0.f;

    auto loadTiles = [&](int st, int k0) {
        float* a = sA_ + st * ASZ;
        float* b = sB_ + st * BSZ;
        #pragma unroll
        for (int i = tid; i < BM * 8; i += THREADS) {
            int r = i >> 3, kq = i & 7;
            bool val = (row0 + r < cnt);
            long long ar = 0;
            if (val) {
                if (mode == 1)      ar = stok[r];
                else if (mode == 2) ar = start + row0 + r;
                else                ar = row0 + r;
            }
            cpasync16(a + r * ASTRIDE + kq * 4, Az + ar * lda + k0 + kq * 4, val ? 16 : 0);
        }
        if (!TRANSB) {
            #pragma unroll
            for (int i = tid; i < BK * (BN / 4); i += THREADS) {
                int kk = i >> 5, nq = i & 31;
                cpasync16(b + kk * (BN + 8) + nq * 4,
                          Bz + (long long)(k0 + kk) * ldb + col0 + nq * 4, 16);
            }
        } else {
            #pragma unroll
            for (int i = tid; i < BN * 8; i += THREADS) {
                int n = i >> 3, kq = i & 7;
                cpasync16(b + n * ASTRIDE + kq * 4,
                          Bz + (long long)(col0 + n) * ldb + k0 + kq * 4, 16);
            }
        }
    };

    auto compute = [&](int st) {
        const float* a_ = sA_ + st * ASZ;
        const float* b_ = sB_ + st * BSZ;
        #pragma unroll
        for (int ks = 0; ks < 4; ks++) {
            int kb = ks * 8;
            uint32_t a[FM][4], b[FN][2];
            #pragma unroll
            for (int fm = 0; fm < FM; fm++) {
                int m0 = wr + fm * 16;
                a[fm][0] = rnd(a_[(m0 + g) * ASTRIDE + kb + t]);
                a[fm][1] = rnd(a_[(m0 + g + 8) * ASTRIDE + kb + t]);
                a[fm][2] = rnd(a_[(m0 + g) * ASTRIDE + kb + t + 4]);
                a[fm][3] = rnd(a_[(m0 + g + 8) * ASTRIDE + kb + t + 4]);
            }
            #pragma unroll
            for (int fn = 0; fn < FN; fn++) {
                int n0 = wc + fn * 8 + g;
                if (TRANSB) {
                    b[fn][0] = rnd(b_[n0 * ASTRIDE + kb + t]);
                    b[fn][1] = rnd(b_[n0 * ASTRIDE + kb + t + 4]);
                } else {
                    b[fn][0] = rnd(b_[(kb + t) * (BN + 8) + n0]);
                    b[fn][1] = rnd(b_[(kb + t + 4) * (BN + 8) + n0]);
                }
            }
            #pragma unroll
            for (int fm = 0; fm < FM; fm++)
                #pragma unroll
                for (int fn = 0; fn < FN; fn++) {
                    asm volatile(
                        "mma.sync.aligned.m16n8k8.row.col.f32.tf32.tf32.f32 "
                        "{%0,%1,%2,%3}, {%4,%5,%6,%7}, {%8,%9}, {%0,%1,%2,%3};"
                        : "+f"(acc[fm][fn][0]), "+f"(acc[fm][fn][1]),
                          "+f"(acc[fm][fn][2]), "+f"(acc[fm][fn][3])
                        : "r"(a[fm][0]), "r"(a[fm][1]), "r"(a[fm][2]), "r"(a[fm][3]),
                          "r"(b[fn][0]), "r"(b[fn][1]));
                }
        }
    };

    int kLimit = trimK ? (row0 + BM < K ? row0 + BM : K) : K;
    int nk = kLimit / BK;

    loadTiles(0, 0);      cpasync_commit();
    loadTiles(1, BK);     cpasync_commit();
    for (int ks = 0; ks < nk; ks++) {
        asm volatile("cp.async.wait_group 1;" ::: "memory");
        __syncthreads();
        if (ks + 2 < nk) loadTiles((ks + 2) % 3, (ks + 2) * BK);
        cpasync_commit();
        compute(ks % 3);
    }

    // ---- epilogue ----
    #pragma unroll
    for (int fm = 0; fm < FM; fm++) {
        #pragma unroll
        for (int rr = 0; rr < 2; rr++) {
            int lr = wr + fm * 16 + g + rr * 8;
            if (row0 + lr >= cnt) continue;
            long long crow = (mode == 1 || mode == 2) ? (long long)(start + row0 + lr)
                                                      : (long long)(row0 + lr);
            float* cp = Cz + crow * ldc;
            const float* rp = resid ? (resid + (long long)(row0 + lr) * ldc) : nullptr;
            #pragma unroll
            for (int fn = 0; fn < FN; fn++) {
                int c = col0 + wc + fn * 8 + t * 2;
                float v0 = alpha * acc[fm][fn][rr * 2 + 0];
                float v1 = alpha * acc[fm][fn][rr * 2 + 1];
                if (rp) { v0 += rp[c]; v1 += rp[c + 1]; }
                cp[c] = v0;
                cp[c + 1] = v1;
            }
        }
    }
}

// ---------------- host launcher ----------------
static void* symaddr(const void* s) { void* p = nullptr; cudaGetSymbolAddress(&p, s); return p; }

extern "C" void kernel_launch(void* const* d_in, const int* in_sizes, int n_in,
                              void* d_out, int out_size) {
    const float* x   = (const float*)d_in[0];
    const float* ln1 = (const float*)d_in[1];
    const float* ln2 = (const float*)d_in[2];
    const float* qnw = (const float*)d_in[3];
    const float* knw = (const float*)d_in[4];
    const float* Wq  = (const float*)d_in[5];
    const float* Wk  = (const float*)d_in[6];
    const float* Wv  = (const float*)d_in[7];
    const float* Wo  = (const float*)d_in[8];
    const float* Wg  = (const float*)d_in[9];
    const float* Wgu = (const float*)d_in[10];
    const float* Wd  = (const float*)d_in[11];
    float* out = (float*)d_out;

    float* h1   = (float*)symaddr(g_h1);
    float* q    = (float*)symaddr(g_q);
    float* k    = (float*)symaddr(g_k);
    float* v    = (float*)symaddr(g_v);
    float* sc   = (float*)symaddr(g_scores);
    float* attn = (float*)symaddr(g_attn);
    float* h    = (float*)symaddr(g_h);
    float* h2   = (float*)symaddr(g_h2);
    float* lg   = (float*)symaddr(g_logits);
    float* tw   = (float*)symaddr(g_tw);
    int*   te   = (int*)symaddr(g_te);
    int*   cnts = (int*)symaddr(g_counts);
    int*   offs = (int*)symaddr(g_offsets);
    int*   cur  = (int*)symaddr(g_cursor);
    int*   btok = (int*)symaddr(g_btok);
    int*   ppos = (int*)symaddr(g_ppos);
    float* gu   = (float*)symaddr(g_gu);
    float* act  = (float*)symaddr(g_act);
    float* ybuf = (float*)symaddr(g_ybuf);

    const float scale = 0.08838834764831843f;   // 1/sqrt(128)

    // smem sizes (floats -> bytes)
    const size_t smem128  = (size_t)(3 * 128 * ASTRIDE + 3 * (BK * (128 + 8))) * 4; // 107.5 KB
    const size_t smem128t = (size_t)(3 * 128 * ASTRIDE + 3 * (128 * ASTRIDE)) * 4;  // 110.6 KB
    const size_t smem256  = (size_t)(3 * 256 * ASTRIDE + 3 * (BK * (128 + 8))) * 4; // 162.8 KB
    static int attrDone = 0;
    if (!attrDone) {
        cudaFuncSetAttribute((const void*)gemm_tc<128,0>,
                             cudaFuncAttributeMaxDynamicSharedMemorySize, 120 * 1024);
        cudaFuncSetAttribute((const void*)gemm_tc<128,1>,
                             cudaFuncAttributeMaxDynamicSharedMemorySize, 120 * 1024);
        cudaFuncSetAttribute((const void*)gemm_tc<256,0>,
                             cudaFuncAttributeMaxDynamicSharedMemorySize, 170 * 1024);
        attrDone = 1;
    }

    zero32_kernel<<<1, 32>>>(cnts, cur);

    // ---- attention ----
    rmsnorm_kernel<<<SQ, 256>>>(x, ln1, h1, HDM);

    // fused QKV projection: BM=256, 512 threads, grid (1,4,40)
    gemm_tc<256,0><<<dim3(1, SQ/256, 40), 512, smem256>>>(h1, Wq, q, nullptr,
        SQ, HDM, HDM, 0, 0, 0, 0, 0, 1, 0, 0, 1.f, 3,
        nullptr, nullptr, nullptr, Wk, k, Wv, v);

    qknorm_rope_kernel<<<dim3(NHQ + NKVH, SQ), 128>>>(q, k, qnw, knw);

    // scores = q @ k^T (causal skip)
    gemm_tc<128,1><<<dim3(8, 8, NHQ), 256, smem128t>>>(q, k, sc, nullptr,
        SQ, HDHD, NHQ*HDHD, NKVH*HDHD, SQ,
        HDHD, HDHD, (long long)SQ*SQ, 8, 1, 0, scale, 0,
        nullptr, nullptr, nullptr, nullptr, nullptr, nullptr, nullptr);

    softmax_kernel<<<dim3(SQ, NHQ), 256>>>(sc);

    // attn = probs @ v (K trimmed at diagonal)
    gemm_tc<128,0><<<dim3(1, 8, NHQ), 256, smem128>>>(sc, v, attn, nullptr,
        SQ, SQ, SQ, NKVH*HDHD, NHQ*HDHD,
        (long long)SQ*SQ, HDHD, HDHD, 8, 0, 1, 1.f, 0,
        nullptr, nullptr, nullptr, nullptr, nullptr, nullptr, nullptr);

    // h = x + attn @ Wo   (residual fused)
    gemm_tc<128,0><<<dim3(16, 8, 1), 256, smem128>>>(attn, Wo, h, x,
        SQ, NHQ*HDHD, NHQ*HDHD, HDM, HDM,
        0, 0, 0, 1, 0, 0, 1.f, 0,
        nullptr, nullptr, nullptr, nullptr, nullptr, nullptr, nullptr);

    // ---- MoE ----
    rmsnorm_kernel<<<SQ, 256>>>(h, ln2, h2, HDM);

    gemm_simt_kernel<<<dim3(1, 16, 1), 256>>>(h2, Wg, lg, SQ, NE, HDM, HDM, NE, NE);
    topk_kernel<<<4, 256>>>(lg, tw, te);
    count_kernel<<<(NPAIR + 255) / 256, 256>>>(te, cnts);
    scan_kernel<<<1, 32>>>(cnts, offs);
    assign_kernel<<<(NPAIR + 255) / 256, 256>>>(te, offs, cur, btok, ppos);

    // MoE up/gate: BM=256, covers up to 2048 rows/expert (y=8)
    gemm_tc<256,0><<<dim3(2*IDIM/128, 8, NE), 512, smem256>>>(h2, Wgu, gu, nullptr,
        SQ, HDM, HDM, 2*IDIM, 2*IDIM,
        0, (long long)HDM*2*IDIM, 0, 1, 0, 0, 1.f, 1,
        cnts, offs, btok, nullptr, nullptr, nullptr, nullptr);

    silu_kernel<<<(int)(((long long)NPAIR*IDIM + 255) / 256), 256>>>(gu, act);

    // MoE down: BM=256
    gemm_tc<256,0><<<dim3(HDM/128, 8, NE), 512, smem256>>>(act, Wd, ybuf, nullptr,
        SQ, IDIM, IDIM, HDM, HDM,
        0, (long long)IDIM*HDM, 0, 1, 0, 0, 1.f, 2,
        cnts, offs, nullptr, nullptr, nullptr, nullptr, nullptr);

    combine_kernel<<<SQ, 256>>>(h, ybuf, ppos, tw, out);
}

// round 10
// speedup vs baseline: 1.3237x; 1.0416x over previous
#include <cuda_runtime.h>
#include <math.h>
#include <stdint.h>

// ---------------- problem constants ----------------
#define SQ   1024
#define HDM  2048
#define NHQ  32
#define NKVH 4
#define HDHD 128
#define NE   32
#define TOPK 8
#define IDIM 768
#define NPAIR (SQ*TOPK)   // 8192

// ---------------- device scratch ----------------
__device__ float g_h1[SQ*HDM];
__device__ float g_q [SQ*NHQ*HDHD];
__device__ float g_k [SQ*NKVH*HDHD];
__device__ float g_v [SQ*NKVH*HDHD];
__device__ float g_scores[(long long)NHQ*SQ*SQ];
__device__ float g_attn[SQ*NHQ*HDHD];
__device__ float g_h [SQ*HDM];
__device__ float g_h2[SQ*HDM];
__device__ float g_logits[SQ*NE];
__device__ float g_tw[NPAIR];
__device__ int   g_te[NPAIR];
__device__ int   g_counts[NE];
__device__ int   g_offsets[NE];
__device__ int   g_cursor[NE];
__device__ int   g_btok[NPAIR];
__device__ int   g_ppos[NPAIR];
__device__ float g_gu [(long long)NPAIR*2*IDIM];
__device__ float g_act[(long long)NPAIR*IDIM];
__device__ float g_ybuf[(long long)NPAIR*HDM];

// ---------------- helpers ----------------
__device__ __forceinline__ void cpasync16(void* dst, const void* src, int srcsize) {
    uint32_t d = (uint32_t)__cvta_generic_to_shared(dst);
    asm volatile("cp.async.cg.shared.global [%0], [%1], 16, %2;"
                 :: "r"(d), "l"(src), "r"(srcsize) : "memory");
}
__device__ __forceinline__ void cpasync_commit() {
    asm volatile("cp.async.commit_group;" ::: "memory");
}
// round-to-nearest-away into tf32's 19 kept bits (mma ignores low 13 bits)
__device__ __forceinline__ uint32_t rnd(float v) {
    return __float_as_uint(v) + 0x1000u;
}

// ---------------- small kernels ----------------
__global__ void zero32_kernel(int* counts, int* cursor) {
    int i = threadIdx.x;
    if (i < NE) { counts[i] = 0; cursor[i] = 0; }
}

__global__ void rmsnorm_kernel(const float* __restrict__ x, const float* __restrict__ w,
                               float* __restrict__ o, int ncols) {
    int row = blockIdx.x;
    const float* xr = x + (long long)row * ncols;
    float* orow = o + (long long)row * ncols;
    __shared__ float red[256];
    float s = 0.f;
    for (int c = threadIdx.x; c < ncols; c += 256) { float t = xr[c]; s += t * t; }
    red[threadIdx.x] = s; __syncthreads();
    for (int st = 128; st > 0; st >>= 1) {
        if (threadIdx.x < st) red[threadIdx.x] += red[threadIdx.x + st];
        __syncthreads();
    }
    float rms = rsqrtf(red[0] / (float)ncols + 1e-6f);
    for (int c = threadIdx.x; c < ncols; c += 256) orow[c] = xr[c] * rms * w[c];
}

__global__ void qknorm_rope_kernel(float* __restrict__ q, float* __restrict__ k,
                                   const float* __restrict__ qw, const float* __restrict__ kw) {
    int slot = blockIdx.x;
    int t    = blockIdx.y;
    float* vec; const float* w;
    if (slot < NHQ) { vec = q + (long long)t * (NHQ*HDHD) + slot * HDHD; w = qw; }
    else            { vec = k + (long long)t * (NKVH*HDHD) + (slot - NHQ) * HDHD; w = kw; }
    int d = threadIdx.x;
    float v = vec[d];
    float s = v * v;
    #pragma unroll
    for (int o = 16; o > 0; o >>= 1) s += __shfl_xor_sync(0xffffffffu, s, o);
    __shared__ float red[4];
    if ((d & 31) == 0) red[d >> 5] = s;
    __syncthreads();
    float tot = red[0] + red[1] + red[2] + red[3];
    float rms = rsqrtf(tot / 128.f + 1e-6f);
    float nv = v * rms * w[d];
    __shared__ float sv[128];
    sv[d] = nv;
    __syncthreads();
    int d2 = d & 63;
    float angle = (float)t * powf(10000.0f, -(float)(2 * d2) / 128.0f);
    float c = cosf(angle), sn = sinf(angle);
    float other = (d < 64) ? -sv[d + 64] : sv[d - 64];
    vec[d] = nv * c + other * sn;
}

__global__ void softmax_kernel(float* __restrict__ scores) {
    int i = blockIdx.x, h = blockIdx.y;
    float* row = scores + ((long long)h * SQ + i) * SQ;
    int len = i + 1;
    __shared__ float red[256];
    float m = -1e30f;
    for (int j = threadIdx.x; j < len; j += 256) m = fmaxf(m, row[j]);
    red[threadIdx.x] = m; __syncthreads();
    for (int st = 128; st > 0; st >>= 1) {
        if (threadIdx.x < st) red[threadIdx.x] = fmaxf(red[threadIdx.x], red[threadIdx.x + st]);
        __syncthreads();
    }
    m = red[0]; __syncthreads();
    float s = 0.f;
    for (int j = threadIdx.x; j < len; j += 256) { float e = __expf(row[j] - m); row[j] = e; s += e; }
    red[threadIdx.x] = s; __syncthreads();
    for (int st = 128; st > 0; st >>= 1) {
        if (threadIdx.x < st) red[threadIdx.x] += red[threadIdx.x + st];
        __syncthreads();
    }
    float inv = 1.f / red[0];
    int fill = ((i >> 7) + 1) << 7;   // AV K-loop trims at 128-block boundary
    for (int j = threadIdx.x; j < fill; j += 256) row[j] = (j < len) ? row[j] * inv : 0.f;
}

__global__ void topk_kernel(const float* __restrict__ logits, float* __restrict__ tw,
                            int* __restrict__ te) {
    int t = blockIdx.x * blockDim.x + threadIdx.x;
    if (t >= SQ) return;
    float p[NE];
    float m = -1e30f;
    for (int e = 0; e < NE; e++) { p[e] = logits[t * NE + e]; m = fmaxf(m, p[e]); }
    float s = 0.f;
    for (int e = 0; e < NE; e++) { p[e] = expf(p[e] - m); s += p[e]; }
    float inv = 1.f / s;
    bool used[NE];
    for (int e = 0; e < NE; e++) used[e] = false;
    for (int kk = 0; kk < TOPK; kk++) {
        int best = -1; float bv = -1e30f;
        for (int e = 0; e < NE; e++)
            if (!used[e] && p[e] > bv) { bv = p[e]; best = e; }
        used[best] = true;
        te[t * TOPK + kk] = best;
        tw[t * TOPK + kk] = p[best] * inv;
    }
}

__global__ void count_kernel(const int* __restrict__ te, int* __restrict__ counts) {
    int p = blockIdx.x * 256 + threadIdx.x;
    if (p < NPAIR) atomicAdd(&counts[te[p]], 1);
}

__global__ void scan_kernel(const int* __restrict__ counts, int* __restrict__ offsets) {
    if (threadIdx.x == 0) {
        int s = 0;
        for (int e = 0; e < NE; e++) { offsets[e] = s; s += counts[e]; }
    }
}

__global__ void assign_kernel(const int* __restrict__ te, const int* __restrict__ offsets,
                              int* __restrict__ cursor, int* __restrict__ btok,
                              int* __restrict__ ppos) {
    int p = blockIdx.x * 256 + threadIdx.x;
    if (p >= NPAIR) return;
    int e = te[p];
    int pos = offsets[e] + atomicAdd(&cursor[e], 1);
    btok[pos] = p >> 3;
    ppos[p] = pos;
}

__global__ void silu_kernel(const float* __restrict__ gu, float* __restrict__ act) {
    long long idx = (long long)blockIdx.x * 256 + threadIdx.x;
    if (idx >= (long long)NPAIR * IDIM) return;
    long long p = idx / IDIM, f = idx % IDIM;
    float g = gu[p * (2 * IDIM) + f];
    float u = gu[p * (2 * IDIM) + IDIM + f];
    act[idx] = (g / (1.f + __expf(-g))) * u;
}

__global__ void combine_kernel(const float* __restrict__ h, const float* __restrict__ ybuf,
                               const int* __restrict__ ppos, const float* __restrict__ tw,
                               float* __restrict__ out) {
    int t = blockIdx.x;
    __shared__ int   pos[TOPK];
    __shared__ float ww[TOPK];
    if (threadIdx.x < TOPK) {
        pos[threadIdx.x] = ppos[t * TOPK + threadIdx.x];
        ww[threadIdx.x]  = tw[t * TOPK + threadIdx.x];
    }
    __syncthreads();
    const float4* h4 = (const float4*)(h + (long long)t * HDM);
    float4* o4 = (float4*)(out + (long long)t * HDM);
    for (int c = threadIdx.x; c < HDM / 4; c += 256) {
        float4 a = h4[c];
        #pragma unroll
        for (int kk = 0; kk < TOPK; kk++) {
            float4 b = ((const float4*)(ybuf + (long long)pos[kk] * HDM))[c];
            float wv = ww[kk];
            a.x += wv * b.x; a.y += wv * b.y; a.z += wv * b.z; a.w += wv * b.w;
        }
        o4[c] = a;
    }
}

// ---------------- exact fp32 SIMT GEMM (gate logits only) ----------------
__global__ void gemm_simt_kernel(const float* __restrict__ A, const float* __restrict__ B,
                                 float* __restrict__ C, int M, int N, int K,
                                 int lda, int ldb, int ldc) {
    __shared__ float As[16][64 + 4];
    __shared__ float Bs[16][64];
    int tid = threadIdx.x;
    int tx = tid & 15, ty = tid >> 4;
    int row0 = blockIdx.y * 64;
    int col0 = blockIdx.x * 64;
    float acc[4][4] = {};
    for (int k0 = 0; k0 < K; k0 += 16) {
        for (int i = tid; i < 64 * 16; i += 256) {
            int m = i >> 4, kk = i & 15;
            int gr = row0 + m;
            As[kk][m] = (gr < M) ? A[(long long)gr * lda + k0 + kk] : 0.f;
        }
        for (int i = tid; i < 16 * 64; i += 256) {
            int kk = i >> 6, n = i & 63;
            int gc = col0 + n;
            Bs[kk][n] = (gc < N) ? B[(long long)(k0 + kk) * ldb + gc] : 0.f;
        }
        __syncthreads();
        #pragma unroll
        for (int kk = 0; kk < 16; kk++) {
            float a[4], b[4];
            #pragma unroll
            for (int i = 0; i < 4; i++) a[i] = As[kk][ty * 4 + i];
            #pragma unroll
            for (int j = 0; j < 4; j++) b[j] = Bs[kk][tx * 4 + j];
            #pragma unroll
            for (int i = 0; i < 4; i++)
                #pragma unroll
                for (int j = 0; j < 4; j++)
                    acc[i][j] += a[i] * b[j];
        }
        __syncthreads();
    }
    #pragma unroll
    for (int i = 0; i < 4; i++) {
        int r = row0 + ty * 4 + i;
        if (r >= M) continue;
        #pragma unroll
        for (int j = 0; j < 4; j++) {
            int c = col0 + tx * 4 + j;
            if (c < N) C[(long long)r * ldc + c] = acc[i][j];
        }
    }
}

// ---------------- tf32 tensor-core GEMM, BK=32, 3-stage cp.async ----------------
// BM=128 fixed, 256 threads, 8 warps. BN=128: warp tile 64x32; BN=256: warp tile 64x64.
// modes: 0 = batched; 1 = gathered rows via btok; 2 = contiguous rows from offsets;
//        3 = fused QKV (B/C = Wq/q, B2/C2 = Wk/k, B3/C3 = Wv/v)
#define BK 32
#define ASTRIDE 36
template<int BN, int TRANSB>
__global__ void __launch_bounds__(256, 1)
gemm_tc(const float* __restrict__ A, const float* __restrict__ B, float* __restrict__ C,
        const float* __restrict__ resid,
        int M, int K, int lda, int ldb, int ldc,
        long long sA, long long sB, long long sC, int bDivB,
        int causal, int trimK, float alpha, int mode,
        const int* __restrict__ counts, const int* __restrict__ offsets,
        const int* __restrict__ btok,
        const float* __restrict__ B2, float* __restrict__ C2,
        const float* __restrict__ B3, float* __restrict__ C3) {
    constexpr int BM = 128;
    constexpr int THREADS = 256;
    constexpr int WN = BN / 4;            // 32 or 64
    constexpr int FM = 4, FN = WN / 8;    // 4 or 8
    constexpr int ASZ = BM * ASTRIDE;
    constexpr int BSZ = TRANSB ? (BN * ASTRIDE) : (BK * (BN + 8));

    extern __shared__ float smem[];
    float* sA_ = smem;                 // 3 stages of A
    float* sB_ = smem + 3 * ASZ;       // 3 stages of B
    __shared__ int stok[BM];

    int z = blockIdx.z;
    int tid = threadIdx.x;
    int row0 = blockIdx.y * BM;
    int col0 = blockIdx.x * BN;

    const float* Az = A;
    const float* Bz;
    float* Cz;
    if (mode == 0) {
        Az = A + (long long)z * sA;
        Bz = B + (long long)(z / bDivB) * sB;
        Cz = C + (long long)z * sC;
    } else if (mode == 3) {
        // BN=256: z<16 -> Q, 16..17 -> K, 18..19 -> V
        if (z < 16)      { Bz = B;  Cz = C;  ldb = ldc = NHQ*HDHD;  col0 = z * BN; }
        else if (z < 18) { Bz = B2; Cz = C2; ldb = ldc = NKVH*HDHD; col0 = (z - 16) * BN; }
        else             { Bz = B3; Cz = C3; ldb = ldc = NKVH*HDHD; col0 = (z - 18) * BN; }
    } else {
        Bz = B + (long long)z * sB;
        Cz = C;
    }

    int cnt = M, start = 0;
    if (mode == 1 || mode == 2) { cnt = counts[z]; start = offsets[z]; }
    if ((mode == 1 || mode == 2) && row0 >= cnt) return;
    if (causal && col0 > row0) return;

    if (mode == 1) {
        for (int i = tid; i < BM; i += THREADS)
            stok[i] = (row0 + i < cnt) ? btok[start + row0 + i] : 0;
        __syncthreads();
    }

    int warp = tid >> 5, lane = tid & 31;
    int wr = (warp >> 2) * 64, wc = (warp & 3) * WN;
    int g = lane >> 2, t = lane & 3;

    float acc[FM][FN][4];
    #pragma unroll
    for (int i = 0; i < FM; i++)
        #pragma unroll
        for (int j = 0; j < FN; j++)
            #pragma unroll
            for (int r = 0; r < 4; r++) acc[i][j][r] = 0.f;

    auto loadTiles = [&](int st, int k0) {
        float* a = sA_ + st * ASZ;
        float* b = sB_ + st * BSZ;
        #pragma unroll
        for (int i = tid; i < BM * 8; i += THREADS) {
            int r = i >> 3, kq = i & 7;
            bool val = (row0 + r < cnt);
            long long ar = 0;
            if (val) {
                if (mode == 1)      ar = stok[r];
                else if (mode == 2) ar = start + row0 + r;
                else                ar = row0 + r;
            }
            cpasync16(a + r * ASTRIDE + kq * 4, Az + ar * lda + k0 + kq * 4, val ? 16 : 0);
        }
        if (!TRANSB) {
            #pragma unroll
            for (int i = tid; i < BK * (BN / 4); i += THREADS) {
                int kk = i / (BN / 4), nq = i % (BN / 4);
                cpasync16(b + kk * (BN + 8) + nq * 4,
                          Bz + (long long)(k0 + kk) * ldb + col0 + nq * 4, 16);
            }
        } else {
            #pragma unroll
            for (int i = tid; i < BN * 8; i += THREADS) {
                int n = i >> 3, kq = i & 7;
                cpasync16(b + n * ASTRIDE + kq * 4,
                          Bz + (long long)(col0 + n) * ldb + k0 + kq * 4, 16);
            }
        }
    };

    auto compute = [&](int st) {
        const float* a_ = sA_ + st * ASZ;
        const float* b_ = sB_ + st * BSZ;
        #pragma unroll
        for (int ks = 0; ks < 4; ks++) {
            int kb = ks * 8;
            uint32_t a[FM][4], b[FN][2];
            #pragma unroll
            for (int fm = 0; fm < FM; fm++) {
                int m0 = wr + fm * 16;
                a[fm][0] = rnd(a_[(m0 + g) * ASTRIDE + kb + t]);
                a[fm][1] = rnd(a_[(m0 + g + 8) * ASTRIDE + kb + t]);
                a[fm][2] = rnd(a_[(m0 + g) * ASTRIDE + kb + t + 4]);
                a[fm][3] = rnd(a_[(m0 + g + 8) * ASTRIDE + kb + t + 4]);
            }
            #pragma unroll
            for (int fn = 0; fn < FN; fn++) {
                int n0 = wc + fn * 8 + g;
                if (TRANSB) {
                    b[fn][0] = rnd(b_[n0 * ASTRIDE + kb + t]);
                    b[fn][1] = rnd(b_[n0 * ASTRIDE + kb + t + 4]);
                } else {
                    b[fn][0] = rnd(b_[(kb + t) * (BN + 8) + n0]);
                    b[fn][1] = rnd(b_[(kb + t + 4) * (BN + 8) + n0]);
                }
            }
            #pragma unroll
            for (int fm = 0; fm < FM; fm++)
                #pragma unroll
                for (int fn = 0; fn < FN; fn++) {
                    asm volatile(
                        "mma.sync.aligned.m16n8k8.row.col.f32.tf32.tf32.f32 "
                        "{%0,%1,%2,%3}, {%4,%5,%6,%7}, {%8,%9}, {%0,%1,%2,%3};"
                        : "+f"(acc[fm][fn][0]), "+f"(acc[fm][fn][1]),
                          "+f"(acc[fm][fn][2]), "+f"(acc[fm][fn][3])
                        : "r"(a[fm][0]), "r"(a[fm][1]), "r"(a[fm][2]), "r"(a[fm][3]),
                          "r"(b[fn][0]), "r"(b[fn][1]));
                }
        }
    };

    int kLimit = trimK ? (row0 + BM < K ? row0 + BM : K) : K;
    int nk = kLimit / BK;

    loadTiles(0, 0);      cpasync_commit();
    loadTiles(1, BK);     cpasync_commit();
    for (int ks = 0; ks < nk; ks++) {
        asm volatile("cp.async.wait_group 1;" ::: "memory");
        __syncthreads();
        if (ks + 2 < nk) loadTiles((ks + 2) % 3, (ks + 2) * BK);
        cpasync_commit();
        compute(ks % 3);
    }

    // ---- epilogue ----
    #pragma unroll
    for (int fm = 0; fm < FM; fm++) {
        #pragma unroll
        for (int rr = 0; rr < 2; rr++) {
            int lr = wr + fm * 16 + g + rr * 8;
            if (row0 + lr >= cnt) continue;
            long long crow = (mode == 1 || mode == 2) ? (long long)(start + row0 + lr)
                                                      : (long long)(row0 + lr);
            float* cp = Cz + crow * ldc;
            const float* rp = resid ? (resid + (long long)(row0 + lr) * ldc) : nullptr;
            #pragma unroll
            for (int fn = 0; fn < FN; fn++) {
                int c = col0 + wc + fn * 8 + t * 2;
                float v0 = alpha * acc[fm][fn][rr * 2 + 0];
                float v1 = alpha * acc[fm][fn][rr * 2 + 1];
                if (rp) { v0 += rp[c]; v1 += rp[c + 1]; }
                cp[c] = v0;
                cp[c + 1] = v1;
            }
        }
    }
}

// ---------------- host launcher ----------------
static void* symaddr(const void* s) { void* p = nullptr; cudaGetSymbolAddress(&p, s); return p; }

extern "C" void kernel_launch(void* const* d_in, const int* in_sizes, int n_in,
                              void* d_out, int out_size) {
    const float* x   = (const float*)d_in[0];
    const float* ln1 = (const float*)d_in[1];
    const float* ln2 = (const float*)d_in[2];
    const float* qnw = (const float*)d_in[3];
    const float* knw = (const float*)d_in[4];
    const float* Wq  = (const float*)d_in[5];
    const float* Wk  = (const float*)d_in[6];
    const float* Wv  = (const float*)d_in[7];
    const float* Wo  = (const float*)d_in[8];
    const float* Wg  = (const float*)d_in[9];
    const float* Wgu = (const float*)d_in[10];
    const float* Wd  = (const float*)d_in[11];
    float* out = (float*)d_out;

    float* h1   = (float*)symaddr(g_h1);
    float* q    = (float*)symaddr(g_q);
    float* k    = (float*)symaddr(g_k);
    float* v    = (float*)symaddr(g_v);
    float* sc   = (float*)symaddr(g_scores);
    float* attn = (float*)symaddr(g_attn);
    float* h    = (float*)symaddr(g_h);
    float* h2   = (float*)symaddr(g_h2);
    float* lg   = (float*)symaddr(g_logits);
    float* tw   = (float*)symaddr(g_tw);
    int*   te   = (int*)symaddr(g_te);
    int*   cnts = (int*)symaddr(g_counts);
    int*   offs = (int*)symaddr(g_offsets);
    int*   cur  = (int*)symaddr(g_cursor);
    int*   btok = (int*)symaddr(g_btok);
    int*   ppos = (int*)symaddr(g_ppos);
    float* gu   = (float*)symaddr(g_gu);
    float* act  = (float*)symaddr(g_act);
    float* ybuf = (float*)symaddr(g_ybuf);

    const float scale = 0.08838834764831843f;   // 1/sqrt(128)

    // smem sizes (floats -> bytes)
    const size_t smem128  = (size_t)(3 * 128 * ASTRIDE + 3 * (BK * (128 + 8))) * 4; // 107.5 KB
    const size_t smem128t = (size_t)(3 * 128 * ASTRIDE + 3 * (128 * ASTRIDE)) * 4;  // 110.6 KB
    const size_t smem256  = (size_t)(3 * 128 * ASTRIDE + 3 * (BK * (256 + 8))) * 4; // 156.7 KB
    static int attrDone = 0;
    if (!attrDone) {
        cudaFuncSetAttribute((const void*)gemm_tc<128,0>,
                             cudaFuncAttributeMaxDynamicSharedMemorySize, 120 * 1024);
        cudaFuncSetAttribute((const void*)gemm_tc<128,1>,
                             cudaFuncAttributeMaxDynamicSharedMemorySize, 120 * 1024);
        cudaFuncSetAttribute((const void*)gemm_tc<256,0>,
                             cudaFuncAttributeMaxDynamicSharedMemorySize, 164 * 1024);
        attrDone = 1;
    }

    zero32_kernel<<<1, 32>>>(cnts, cur);

    // ---- attention ----
    rmsnorm_kernel<<<SQ, 256>>>(x, ln1, h1, HDM);

    // fused QKV projection: BN=256 wide warp tiles, grid (1,8,20)
    gemm_tc<256,0><<<dim3(1, 8, 20), 256, smem256>>>(h1, Wq, q, nullptr,
        SQ, HDM, HDM, 0, 0, 0, 0, 0, 1, 0, 0, 1.f, 3,
        nullptr, nullptr, nullptr, Wk, k, Wv, v);

    qknorm_rope_kernel<<<dim3(NHQ + NKVH, SQ), 128>>>(q, k, qnw, knw);

    // scores = q @ k^T (causal skip)
    gemm_tc<128,1><<<dim3(8, 8, NHQ), 256, smem128t>>>(q, k, sc, nullptr,
        SQ, HDHD, NHQ*HDHD, NKVH*HDHD, SQ,
        HDHD, HDHD, (long long)SQ*SQ, 8, 1, 0, scale, 0,
        nullptr, nullptr, nullptr, nullptr, nullptr, nullptr, nullptr);

    softmax_kernel<<<dim3(SQ, NHQ), 256>>>(sc);

    // attn = probs @ v (K trimmed at diagonal)
    gemm_tc<128,0><<<dim3(1, 8, NHQ), 256, smem128>>>(sc, v, attn, nullptr,
        SQ, SQ, SQ, NKVH*HDHD, NHQ*HDHD,
        (long long)SQ*SQ, HDHD, HDHD, 8, 0, 1, 1.f, 0,
        nullptr, nullptr, nullptr, nullptr, nullptr, nullptr, nullptr);

    // h = x + attn @ Wo   (residual fused)
    gemm_tc<128,0><<<dim3(16, 8, 1), 256, smem128>>>(attn, Wo, h, x,
        SQ, NHQ*HDHD, NHQ*HDHD, HDM, HDM,
        0, 0, 0, 1, 0, 0, 1.f, 0,
        nullptr, nullptr, nullptr, nullptr, nullptr, nullptr, nullptr);

    // ---- MoE ----
    rmsnorm_kernel<<<SQ, 256>>>(h, ln2, h2, HDM);

    gemm_simt_kernel<<<dim3(1, 16, 1), 256>>>(h2, Wg, lg, SQ, NE, HDM, HDM, NE, NE);
    topk_kernel<<<4, 256>>>(lg, tw, te);
    count_kernel<<<(NPAIR + 255) / 256, 256>>>(te, cnts);
    scan_kernel<<<1, 32>>>(cnts, offs);
    assign_kernel<<<(NPAIR + 255) / 256, 256>>>(te, offs, cur, btok, ppos);

    // MoE up/gate: BN=256, grid (6,8,32)
    gemm_tc<256,0><<<dim3(2*IDIM/256, 8, NE), 256, smem256>>>(h2, Wgu, gu, nullptr,
        SQ, HDM, HDM, 2*IDIM, 2*IDIM,
        0, (long long)HDM*2*IDIM, 0, 1, 0, 0, 1.f, 1,
        cnts, offs, btok, nullptr, nullptr, nullptr, nullptr);

    silu_kernel<<<(int)(((long long)NPAIR*IDIM + 255) / 256), 256>>>(gu, act);

    // MoE down: BN=256, grid (8,8,32)
    gemm_tc<256,0><<<dim3(HDM/256, 8, NE), 256, smem256>>>(act, Wd, ybuf, nullptr,
        SQ, IDIM, IDIM, HDM, HDM,
        0, (long long)IDIM*HDM, 0, 1, 0, 0, 1.f, 2,
        cnts, offs, nullptr, nullptr, nullptr, nullptr, nullptr);

    combine_kernel<<<SQ, 256>>>(h, ybuf, ppos, tw, out);
}

// round 13
// speedup vs baseline: 1.3923x; 1.0518x over previous
#include <cuda_runtime.h>
#include <math.h>
#include <stdint.h>

// ---------------- problem constants ----------------
#define SQ   1024
#define HDM  2048
#define NHQ  32
#define NKVH 4
#define HDHD 128
#define NE   32
#define TOPK 8
#define IDIM 768
#define NPAIR (SQ*TOPK)   // 8192

// ---------------- device scratch ----------------
__device__ float g_h1[SQ*HDM];
__device__ float g_q [SQ*NHQ*HDHD];
__device__ float g_k [SQ*NKVH*HDHD];
__device__ float g_v [SQ*NKVH*HDHD];
__device__ float g_attn[SQ*NHQ*HDHD];
__device__ float g_h [SQ*HDM];
__device__ float g_h2[SQ*HDM];
__device__ float g_logits[SQ*NE];
__device__ float g_tw[NPAIR];
__device__ int   g_te[NPAIR];
__device__ int   g_counts[NE];
__device__ int   g_offsets[NE];
__device__ int   g_cursor[NE];
__device__ int   g_btok[NPAIR];
__device__ int   g_ppos[NPAIR];
__device__ float g_gu [(long long)NPAIR*2*IDIM];
__device__ float g_act[(long long)NPAIR*IDIM];
__device__ float g_ybuf[(long long)NPAIR*HDM];

// ---------------- helpers ----------------
__device__ __forceinline__ void cpasync16(void* dst, const void* src, int srcsize) {
    uint32_t d = (uint32_t)__cvta_generic_to_shared(dst);
    asm volatile("cp.async.cg.shared.global [%0], [%1], 16, %2;"
                 :: "r"(d), "l"(src), "r"(srcsize) : "memory");
}
__device__ __forceinline__ void cpasync_commit() {
    asm volatile("cp.async.commit_group;" ::: "memory");
}
// round-to-nearest-away into tf32's 19 kept bits (mma ignores low 13 bits)
__device__ __forceinline__ uint32_t rnd(float v) {
    return __float_as_uint(v) + 0x1000u;
}
#define MMA_TF32(acc, a, b) \
    asm volatile( \
        "mma.sync.aligned.m16n8k8.row.col.f32.tf32.tf32.f32 " \
        "{%0,%1,%2,%3}, {%4,%5,%6,%7}, {%8,%9}, {%0,%1,%2,%3};" \
        : "+f"((acc)[0]), "+f"((acc)[1]), "+f"((acc)[2]), "+f"((acc)[3]) \
        : "r"((a)[0]), "r"((a)[1]), "r"((a)[2]), "r"((a)[3]), \
          "r"((b)[0]), "r"((b)[1]))

// ---------------- small kernels ----------------
__global__ void zero32_kernel(int* counts, int* cursor) {
    int i = threadIdx.x;
    if (i < NE) { counts[i] = 0; cursor[i] = 0; }
}

__global__ void rmsnorm_kernel(const float* __restrict__ x, const float* __restrict__ w,
                               float* __restrict__ o, int ncols) {
    int row = blockIdx.x;
    const float* xr = x + (long long)row * ncols;
    float* orow = o + (long long)row * ncols;
    __shared__ float red[256];
    float s = 0.f;
    for (int c = threadIdx.x; c < ncols; c += 256) { float t = xr[c]; s += t * t; }
    red[threadIdx.x] = s; __syncthreads();
    for (int st = 128; st > 0; st >>= 1) {
        if (threadIdx.x < st) red[threadIdx.x] += red[threadIdx.x + st];
        __syncthreads();
    }
    float rms = rsqrtf(red[0] / (float)ncols + 1e-6f);
    for (int c = threadIdx.x; c < ncols; c += 256) orow[c] = xr[c] * rms * w[c];
}

__global__ void qknorm_rope_kernel(float* __restrict__ q, float* __restrict__ k,
                                   const float* __restrict__ qw, const float* __restrict__ kw) {
    int slot = blockIdx.x;
    int t    = blockIdx.y;
    float* vec; const float* w;
    if (slot < NHQ) { vec = q + (long long)t * (NHQ*HDHD) + slot * HDHD; w = qw; }
    else            { vec = k + (long long)t * (NKVH*HDHD) + (slot - NHQ) * HDHD; w = kw; }
    int d = threadIdx.x;
    float v = vec[d];
    float s = v * v;
    #pragma unroll
    for (int o = 16; o > 0; o >>= 1) s += __shfl_xor_sync(0xffffffffu, s, o);
    __shared__ float red[4];
    if ((d & 31) == 0) red[d >> 5] = s;
    __syncthreads();
    float tot = red[0] + red[1] + red[2] + red[3];
    float rms = rsqrtf(tot / 128.f + 1e-6f);
    float nv = v * rms * w[d];
    __shared__ float sv[128];
    sv[d] = nv;
    __syncthreads();
    int d2 = d & 63;
    float angle = (float)t * powf(10000.0f, -(float)(2 * d2) / 128.0f);
    float c = cosf(angle), sn = sinf(angle);
    float other = (d < 64) ? -sv[d + 64] : sv[d - 64];
    vec[d] = nv * c + other * sn;
}

// ---------------- flash attention: scores+softmax+AV fused ----------------
// grid (8 row-blocks, 32 heads), 256 threads. Q tile 128 rows in smem,
// KV streamed in 64-col blocks with online softmax. tf32 mma throughout.
#define FBR 128
#define FBC 64
#define QSTR 164   // 128+36: stride%32==4 -> conflict-free A-frag reads
#define KSTR 164
#define VSTR 136   // stride%32==8 -> conflict-free B-frag reads
#define PSTR 68    // 64+4: stride%32==4
__global__ void __launch_bounds__(256, 1)
flash_kernel(const float* __restrict__ q, const float* __restrict__ k,
             const float* __restrict__ v, float* __restrict__ attn, float scale) {
    int rb = blockIdx.x;
    int h  = blockIdx.y;
    int kv = h >> 3;
    int tid = threadIdx.x;
    int warp = tid >> 5, lane = tid & 31;
    int g = lane >> 2, t = lane & 3;
    int wr  = (warp >> 2) * 64;
    int wcS = (warp & 3) * 16;
    int wcO = (warp & 3) * 32;
    int wq  = warp & 3;

    extern __shared__ float sm[];
    float* Qs   = sm;                       // 128 x QSTR
    float* Ks   = Qs + FBR*QSTR;            // 64 x KSTR
    float* Vs   = Ks + FBC*KSTR;            // 64 x VSTR
    float* Ps   = Vs + FBC*VSTR;            // 128 x PSTR
    float* redm = Ps + FBR*PSTR;            // 4 x 128
    float* redl = redm + 4*FBR;             // 4 x 128
    float* m_s  = redl + 4*FBR;             // 128
    float* l_s  = m_s + FBR;                // 128

    int row0 = rb * FBR;

    for (int i = tid; i < FBR; i += 256) { m_s[i] = -1e30f; l_s[i] = 0.f; }

    // Q tile: 128 rows x 128 floats = 32 16B-chunks per row
    for (int i = tid; i < FBR * 32; i += 256) {
        int r = i >> 5, cq = i & 31;
        cpasync16(Qs + r*QSTR + cq*4,
                  q + (long long)(row0 + r)*(NHQ*HDHD) + h*HDHD + cq*4, 16);
    }
    // K_0, V_0: 64 rows x 128 floats = 32 chunks per row
    for (int i = tid; i < FBC * 32; i += 256) {
        int n = i >> 5, cq = i & 31;
        cpasync16(Ks + n*KSTR + cq*4,
                  k + (long long)n*(NKVH*HDHD) + kv*HDHD + cq*4, 16);
        cpasync16(Vs + n*VSTR + cq*4,
                  v + (long long)n*(NKVH*HDHD) + kv*HDHD + cq*4, 16);
    }
    cpasync_commit();

    float accO[4][4][4];
    #pragma unroll
    for (int i1 = 0; i1 < 4; i1++)
        #pragma unroll
        for (int i2 = 0; i2 < 4; i2++)
            #pragma unroll
            for (int i3 = 0; i3 < 4; i3++) accO[i1][i2][i3] = 0.f;

    int jmax = 2*rb + 1;

    for (int j = 0; j <= jmax; j++) {
        asm volatile("cp.async.wait_group 0;" ::: "memory");
        __syncthreads();

        // ---- S = Q @ K_j^T ----
        float accS[4][2][4];
        #pragma unroll
        for (int i1 = 0; i1 < 4; i1++)
            #pragma unroll
            for (int i2 = 0; i2 < 2; i2++)
                #pragma unroll
                for (int i3 = 0; i3 < 4; i3++) accS[i1][i2][i3] = 0.f;
        #pragma unroll
        for (int ks = 0; ks < 16; ks++) {
            int kb = ks * 8;
            uint32_t a[4][4], b[2][2];
            #pragma unroll
            for (int fm = 0; fm < 4; fm++) {
                int m0 = wr + fm * 16;
                a[fm][0] = rnd(Qs[(m0 + g    ) * QSTR + kb + t    ]);
                a[fm][1] = rnd(Qs[(m0 + g + 8) * QSTR + kb + t    ]);
                a[fm][2] = rnd(Qs[(m0 + g    ) * QSTR + kb + t + 4]);
                a[fm][3] = rnd(Qs[(m0 + g + 8) * QSTR + kb + t + 4]);
            }
            #pragma unroll
            for (int fn = 0; fn < 2; fn++) {
                int n0 = wcS + fn * 8 + g;
                b[fn][0] = rnd(Ks[n0 * KSTR + kb + t    ]);
                b[fn][1] = rnd(Ks[n0 * KSTR + kb + t + 4]);
            }
            #pragma unroll
            for (int fm = 0; fm < 4; fm++)
                #pragma unroll
                for (int fn = 0; fn < 2; fn++)
                    MMA_TF32(accS[fm][fn], a[fm], b[fn]);
        }

        // scale + causal mask + per-row max
        int colbase = j * FBC + wcS;
        #pragma unroll
        for (int fm = 0; fm < 4; fm++)
            #pragma unroll
            for (int rr = 0; rr < 2; rr++) {
                int row = row0 + wr + fm*16 + g + rr*8;
                float mx = -1e30f;
                #pragma unroll
                for (int fn = 0; fn < 2; fn++)
                    #pragma unroll
                    for (int cc = 0; cc < 2; cc++) {
                        float sv = accS[fm][fn][rr*2 + cc] * scale;
                        int col = colbase + fn*8 + t*2 + cc;
                        if (col > row) sv = -1e30f;
                        accS[fm][fn][rr*2 + cc] = sv;
                        mx = fmaxf(mx, sv);
                    }
                mx = fmaxf(mx, __shfl_xor_sync(0xffffffffu, mx, 1));
                mx = fmaxf(mx, __shfl_xor_sync(0xffffffffu, mx, 2));
                if (t == 0) redm[wq*FBR + wr + fm*16 + g + rr*8] = mx;
            }
        __syncthreads();   // redm visible; all warps done reading Ks

        // prefetch K_{j+1} (safe: Ks reads complete)
        if (j < jmax) {
            for (int i = tid; i < FBC * 32; i += 256) {
                int n = i >> 5, cq = i & 31;
                cpasync16(Ks + n*KSTR + cq*4,
                          k + (long long)((j+1)*FBC + n)*(NKVH*HDHD) + kv*HDHD + cq*4, 16);
            }
        }
        cpasync_commit();

        // m_new, rescale factors, P, row sums
        float mnew[4][2], esr[4][2];
        #pragma unroll
        for (int fm = 0; fm < 4; fm++)
            #pragma unroll
            for (int rr = 0; rr < 2; rr++) {
                int row = wr + fm*16 + g + rr*8;
                float mo = m_s[row];
                float mn = fmaxf(fmaxf(redm[row], redm[FBR + row]),
                                 fmaxf(redm[2*FBR + row], redm[3*FBR + row]));
                mn = fmaxf(mn, mo);
                mnew[fm][rr] = mn;
                esr[fm][rr] = __expf(mo - mn);
            }
        #pragma unroll
        for (int fm = 0; fm < 4; fm++)
            #pragma unroll
            for (int rr = 0; rr < 2; rr++) {
                int row = wr + fm*16 + g + rr*8;
                float lsum = 0.f;
                #pragma unroll
                for (int fn = 0; fn < 2; fn++)
                    #pragma unroll
                    for (int cc = 0; cc < 2; cc++) {
                        float p = __expf(accS[fm][fn][rr*2 + cc] - mnew[fm][rr]);
                        lsum += p;
                        Ps[row * PSTR + wcS + fn*8 + t*2 + cc] = p;
                    }
                lsum += __shfl_xor_sync(0xffffffffu, lsum, 1);
                lsum += __shfl_xor_sync(0xffffffffu, lsum, 2);
                if (t == 0) redl[wq*FBR + row] = lsum;
            }
        // rescale O
        #pragma unroll
        for (int fm = 0; fm < 4; fm++)
            #pragma unroll
            for (int fn = 0; fn < 4; fn++)
                #pragma unroll
                for (int r = 0; r < 4; r++)
                    accO[fm][fn][r] *= esr[fm][r >> 1];
        __syncthreads();   // Ps + redl visible; m_s reads complete

        // stats update (unique writer per row) runs concurrently with PV
        if (wq == 0 && t == 0) {
            #pragma unroll
            for (int fm = 0; fm < 4; fm++)
                #pragma unroll
                for (int rr = 0; rr < 2; rr++) {
                    int row = wr + fm*16 + g + rr*8;
                    l_s[row] = l_s[row] * esr[fm][rr]
                             + redl[row] + redl[FBR + row]
                             + redl[2*FBR + row] + redl[3*FBR + row];
                    m_s[row] = mnew[fm][rr];
                }
        }

        // ---- O += P @ V ----
        #pragma unroll
        for (int ks = 0; ks < 8; ks++) {
            int kb = ks * 8;
            uint32_t a[4][4], b[4][2];
            #pragma unroll
            for (int fm = 0; fm < 4; fm++) {
                int m0 = wr + fm * 16;
                a[fm][0] = rnd(Ps[(m0 + g    ) * PSTR + kb + t    ]);
                a[fm][1] = rnd(Ps[(m0 + g + 8) * PSTR + kb + t    ]);
                a[fm][2] = rnd(Ps[(m0 + g    ) * PSTR + kb + t + 4]);
                a[fm][3] = rnd(Ps[(m0 + g + 8) * PSTR + kb + t + 4]);
            }
            #pragma unroll
            for (int fn = 0; fn < 4; fn++) {
                int n0 = wcO + fn * 8 + g;
                b[fn][0] = rnd(Vs[(kb + t    ) * VSTR + n0]);
                b[fn][1] = rnd(Vs[(kb + t + 4) * VSTR + n0]);
            }
            #pragma unroll
            for (int fm = 0; fm < 4; fm++)
                #pragma unroll
                for (int fn = 0; fn < 4; fn++)
                    MMA_TF32(accO[fm][fn], a[fm], b[fn]);
        }
        __syncthreads();   // all warps done reading Vs (and Ps)

        if (j < jmax) {
            for (int i = tid; i < FBC * 32; i += 256) {
                int n = i >> 5, cq = i & 31;
                cpasync16(Vs + n*VSTR + cq*4,
                          v + (long long)((j+1)*FBC + n)*(NKVH*HDHD) + kv*HDHD + cq*4, 16);
            }
        }
        cpasync_commit();
    }

    __syncthreads();   // final l_s updates visible
    #pragma unroll
    for (int fm = 0; fm < 4; fm++)
        #pragma unroll
        for (int rr = 0; rr < 2; rr++) {
            int row = wr + fm*16 + g + rr*8;
            float inv = 1.f / l_s[row];
            float* op = attn + (long long)(row0 + row)*(NHQ*HDHD) + h*HDHD;
            #pragma unroll
            for (int fn = 0; fn < 4; fn++) {
                int c = wcO + fn*8 + t*2;
                op[c]     = accO[fm][fn][rr*2    ] * inv;
                op[c + 1] = accO[fm][fn][rr*2 + 1] * inv;
            }
        }
}

__global__ void topk_kernel(const float* __restrict__ logits, float* __restrict__ tw,
                            int* __restrict__ te) {
    int t = blockIdx.x * blockDim.x + threadIdx.x;
    if (t >= SQ) return;
    float p[NE];
    float m = -1e30f;
    for (int e = 0; e < NE; e++) { p[e] = logits[t * NE + e]; m = fmaxf(m, p[e]); }
    float s = 0.f;
    for (int e = 0; e < NE; e++) { p[e] = expf(p[e] - m); s += p[e]; }
    float inv = 1.f / s;
    bool used[NE];
    for (int e = 0; e < NE; e++) used[e] = false;
    for (int kk = 0; kk < TOPK; kk++) {
        int best = -1; float bv = -1e30f;
        for (int e = 0; e < NE; e++)
            if (!used[e] && p[e] > bv) { bv = p[e]; best = e; }
        used[best] = true;
        te[t * TOPK + kk] = best;
        tw[t * TOPK + kk] = p[best] * inv;
    }
}

__global__ void count_kernel(const int* __restrict__ te, int* __restrict__ counts) {
    int p = blockIdx.x * 256 + threadIdx.x;
    if (p < NPAIR) atomicAdd(&counts[te[p]], 1);
}

__global__ void scan_kernel(const int* __restrict__ counts, int* __restrict__ offsets) {
    if (threadIdx.x == 0) {
        int s = 0;
        for (int e = 0; e < NE; e++) { offsets[e] = s; s += counts[e]; }
    }
}

__global__ void assign_kernel(const int* __restrict__ te, const int* __restrict__ offsets,
                              int* __restrict__ cursor, int* __restrict__ btok,
                              int* __restrict__ ppos) {
    int p = blockIdx.x * 256 + threadIdx.x;
    if (p >= NPAIR) return;
    int e = te[p];
    int pos = offsets[e] + atomicAdd(&cursor[e], 1);
    btok[pos] = p >> 3;
    ppos[p] = pos;
}

__global__ void silu_kernel(const float* __restrict__ gu, float* __restrict__ act) {
    long long idx = (long long)blockIdx.x * 256 + threadIdx.x;
    if (idx >= (long long)NPAIR * IDIM) return;
    long long p = idx / IDIM, f = idx % IDIM;
    float g = gu[p * (2 * IDIM) + f];
    float u = gu[p * (2 * IDIM) + IDIM + f];
    act[idx] = (g / (1.f + __expf(-g))) * u;
}

__global__ void combine_kernel(const float* __restrict__ h, const float* __restrict__ ybuf,
                               const int* __restrict__ ppos, const float* __restrict__ tw,
                               float* __restrict__ out) {
    int t = blockIdx.x;
    __shared__ int   pos[TOPK];
    __shared__ float ww[TOPK];
    if (threadIdx.x < TOPK) {
        pos[threadIdx.x] = ppos[t * TOPK + threadIdx.x];
        ww[threadIdx.x]  = tw[t * TOPK + threadIdx.x];
    }
    __syncthreads();
    const float4* h4 = (const float4*)(h + (long long)t * HDM);
    float4* o4 = (float4*)(out + (long long)t * HDM);
    for (int c = threadIdx.x; c < HDM / 4; c += 256) {
        float4 a = h4[c];
        #pragma unroll
        for (int kk = 0; kk < TOPK; kk++) {
            float4 b = ((const float4*)(ybuf + (long long)pos[kk] * HDM))[c];
            float wv = ww[kk];
            a.x += wv * b.x; a.y += wv * b.y; a.z += wv * b.z; a.w += wv * b.w;
        }
        o4[c] = a;
    }
}

// ---------------- exact fp32 SIMT GEMM (gate logits only) ----------------
__global__ void gemm_simt_kernel(const float* __restrict__ A, const float* __restrict__ B,
                                 float* __restrict__ C, int M, int N, int K,
                                 int lda, int ldb, int ldc) {
    __shared__ float As[16][64 + 4];
    __shared__ float Bs[16][64];
    int tid = threadIdx.x;
    int tx = tid & 15, ty = tid >> 4;
    int row0 = blockIdx.y * 64;
    int col0 = blockIdx.x * 64;
    float acc[4][4] = {};
    for (int k0 = 0; k0 < K; k0 += 16) {
        for (int i = tid; i < 64 * 16; i += 256) {
            int m = i >> 4, kk = i & 15;
            int gr = row0 + m;
            As[kk][m] = (gr < M) ? A[(long long)gr * lda + k0 + kk] : 0.f;
        }
        for (int i = tid; i < 16 * 64; i += 256) {
            int kk = i >> 6, n = i & 63;
            int gc = col0 + n;
            Bs[kk][n] = (gc < N) ? B[(long long)(k0 + kk) * ldb + gc] : 0.f;
        }
        __syncthreads();
        #pragma unroll
        for (int kk = 0; kk < 16; kk++) {
            float a[4], b[4];
            #pragma unroll
            for (int i = 0; i < 4; i++) a[i] = As[kk][ty * 4 + i];
            #pragma unroll
            for (int j = 0; j < 4; j++) b[j] = Bs[kk][tx * 4 + j];
            #pragma unroll
            for (int i = 0; i < 4; i++)
                #pragma unroll
                for (int j = 0; j < 4; j++)
                    acc[i][j] += a[i] * b[j];
        }
        __syncthreads();
    }
    #pragma unroll
    for (int i = 0; i < 4; i++) {
        int r = row0 + ty * 4 + i;
        if (r >= M) continue;
        #pragma unroll
        for (int j = 0; j < 4; j++) {
            int c = col0 + tx * 4 + j;
            if (c < N) C[(long long)r * ldc + c] = acc[i][j];
        }
    }
}

// ---------------- tf32 tensor-core GEMM, BK=32, 3-stage cp.async ----------------
#define BK 32
#define ASTRIDE 36
template<int BN, int TRANSB>
__global__ void __launch_bounds__(256, 1)
gemm_tc(const float* __restrict__ A, const float* __restrict__ B, float* __restrict__ C,
        const float* __restrict__ resid,
        int M, int K, int lda, int ldb, int ldc,
        long long sA, long long sB, long long sC, int bDivB,
        int causal, int trimK, float alpha, int mode,
        const int* __restrict__ counts, const int* __restrict__ offsets,
        const int* __restrict__ btok,
        const float* __restrict__ B2, float* __restrict__ C2,
        const float* __restrict__ B3, float* __restrict__ C3) {
    constexpr int BM = 128;
    constexpr int THREADS = 256;
    constexpr int WN = BN / 4;
    constexpr int FM = 4, FN = WN / 8;
    constexpr int ASZ = BM * ASTRIDE;
    constexpr int BSZ = TRANSB ? (BN * ASTRIDE) : (BK * (BN + 8));

    extern __shared__ float smem[];
    float* sA_ = smem;
    float* sB_ = smem + 3 * ASZ;
    __shared__ int stok[BM];

    int z = blockIdx.z;
    int tid = threadIdx.x;
    int row0 = blockIdx.y * BM;
    int col0 = blockIdx.x * BN;

    const float* Az = A;
    const float* Bz;
    float* Cz;
    if (mode == 0) {
        Az = A + (long long)z * sA;
        Bz = B + (long long)(z / bDivB) * sB;
        Cz = C + (long long)z * sC;
    } else if (mode == 3) {
        if (z < 16)      { Bz = B;  Cz = C;  ldb = ldc = NHQ*HDHD;  col0 = z * BN; }
        else if (z < 18) { Bz = B2; Cz = C2; ldb = ldc = NKVH*HDHD; col0 = (z - 16) * BN; }
        else             { Bz = B3; Cz = C3; ldb = ldc = NKVH*HDHD; col0 = (z - 18) * BN; }
    } else {
        Bz = B + (long long)z * sB;
        Cz = C;
    }

    int cnt = M, start = 0;
    if (mode == 1 || mode == 2) { cnt = counts[z]; start = offsets[z]; }
    if ((mode == 1 || mode == 2) && row0 >= cnt) return;
    if (causal && col0 > row0) return;

    if (mode == 1) {
        for (int i = tid; i < BM; i += THREADS)
            stok[i] = (row0 + i < cnt) ? btok[start + row0 + i] : 0;
        __syncthreads();
    }

    int warp = tid >> 5, lane = tid & 31;
    int wr = (warp >> 2) * 64, wc = (warp & 3) * WN;
    int g = lane >> 2, t = lane & 3;

    float acc[FM][FN][4];
    #pragma unroll
    for (int i = 0; i < FM; i++)
        #pragma unroll
        for (int j = 0; j < FN; j++)
            #pragma unroll
            for (int r = 0; r < 4; r++) acc[i][j][r] = 0.f;

    auto loadTiles = [&](int st, int k0) {
        float* a = sA_ + st * ASZ;
        float* b = sB_ + st * BSZ;
        #pragma unroll
        for (int i = tid; i < BM * 8; i += THREADS) {
            int r = i >> 3, kq = i & 7;
            bool val = (row0 + r < cnt);
            long long ar = 0;
            if (val) {
                if (mode == 1)      ar = stok[r];
                else if (mode == 2) ar = start + row0 + r;
                else                ar = row0 + r;
            }
            cpasync16(a + r * ASTRIDE + kq * 4, Az + ar * lda + k0 + kq * 4, val ? 16 : 0);
        }
        if (!TRANSB) {
            #pragma unroll
            for (int i = tid; i < BK * (BN / 4); i += THREADS) {
                int kk = i / (BN / 4), nq = i % (BN / 4);
                cpasync16(b + kk * (BN + 8) + nq * 4,
                          Bz + (long long)(k0 + kk) * ldb + col0 + nq * 4, 16);
            }
        } else {
            #pragma unroll
            for (int i = tid; i < BN * 8; i += THREADS) {
                int n = i >> 3, kq = i & 7;
                cpasync16(b + n * ASTRIDE + kq * 4,
                          Bz + (long long)(col0 + n) * ldb + k0 + kq * 4, 16);
            }
        }
    };

    auto compute = [&](int st) {
        const float* a_ = sA_ + st * ASZ;
        const float* b_ = sB_ + st * BSZ;
        #pragma unroll
        for (int ks = 0; ks < 4; ks++) {
            int kb = ks * 8;
            uint32_t a[FM][4], b[FN][2];
            #pragma unroll
            for (int fm = 0; fm < FM; fm++) {
                int m0 = wr + fm * 16;
                a[fm][0] = rnd(a_[(m0 + g) * ASTRIDE + kb + t]);
                a[fm][1] = rnd(a_[(m0 + g + 8) * ASTRIDE + kb + t]);
                a[fm][2] = rnd(a_[(m0 + g) * ASTRIDE + kb + t + 4]);
                a[fm][3] = rnd(a_[(m0 + g + 8) * ASTRIDE + kb + t + 4]);
            }
            #pragma unroll
            for (int fn = 0; fn < FN; fn++) {
                int n0 = wc + fn * 8 + g;
                if (TRANSB) {
                    b[fn][0] = rnd(b_[n0 * ASTRIDE + kb + t]);
                    b[fn][1] = rnd(b_[n0 * ASTRIDE + kb + t + 4]);
                } else {
                    b[fn][0] = rnd(b_[(kb + t) * (BN + 8) + n0]);
                    b[fn][1] = rnd(b_[(kb + t + 4) * (BN + 8) + n0]);
                }
            }
            #pragma unroll
            for (int fm = 0; fm < FM; fm++)
                #pragma unroll
                for (int fn = 0; fn < FN; fn++)
                    MMA_TF32(acc[fm][fn], a[fm], b[fn]);
        }
    };

    int kLimit = trimK ? (row0 + BM < K ? row0 + BM : K) : K;
    int nk = kLimit / BK;

    loadTiles(0, 0);      cpasync_commit();
    loadTiles(1, BK);     cpasync_commit();
    for (int ks = 0; ks < nk; ks++) {
        asm volatile("cp.async.wait_group 1;" ::: "memory");
        __syncthreads();
        if (ks + 2 < nk) loadTiles((ks + 2) % 3, (ks + 2) * BK);
        cpasync_commit();
        compute(ks % 3);
    }

    // ---- epilogue ----
    #pragma unroll
    for (int fm = 0; fm < FM; fm++) {
        #pragma unroll
        for (int rr = 0; rr < 2; rr++) {
            int lr = wr + fm * 16 + g + rr * 8;
            if (row0 + lr >= cnt) continue;
            long long crow = (mode == 1 || mode == 2) ? (long long)(start + row0 + lr)
                                                      : (long long)(row0 + lr);
            float* cp = Cz + crow * ldc;
            const float* rp = resid ? (resid + (long long)(row0 + lr) * ldc) : nullptr;
            #pragma unroll
            for (int fn = 0; fn < FN; fn++) {
                int c = col0 + wc + fn * 8 + t * 2;
                float v0 = alpha * acc[fm][fn][rr * 2 + 0];
                float v1 = alpha * acc[fm][fn][rr * 2 + 1];
                if (rp) { v0 += rp[c]; v1 += rp[c + 1]; }
                cp[c] = v0;
                cp[c + 1] = v1;
            }
        }
    }
}

// ---------------- host launcher ----------------
static void* symaddr(const void* s) { void* p = nullptr; cudaGetSymbolAddress(&p, s); return p; }

extern "C" void kernel_launch(void* const* d_in, const int* in_sizes, int n_in,
                              void* d_out, int out_size) {
    const float* x   = (const float*)d_in[0];
    const float* ln1 = (const float*)d_in[1];
    const float* ln2 = (const float*)d_in[2];
    const float* qnw = (const float*)d_in[3];
    const float* knw = (const float*)d_in[4];
    const float* Wq  = (const float*)d_in[5];
    const float* Wk  = (const float*)d_in[6];
    const float* Wv  = (const float*)d_in[7];
    const float* Wo  = (const float*)d_in[8];
    const float* Wg  = (const float*)d_in[9];
    const float* Wgu = (const float*)d_in[10];
    const float* Wd  = (const float*)d_in[11];
    float* out = (float*)d_out;

    float* h1   = (float*)symaddr(g_h1);
    float* q    = (float*)symaddr(g_q);
    float* k    = (float*)symaddr(g_k);
    float* v    = (float*)symaddr(g_v);
    float* attn = (float*)symaddr(g_attn);
    float* h    = (float*)symaddr(g_h);
    float* h2   = (float*)symaddr(g_h2);
    float* lg   = (float*)symaddr(g_logits);
    float* tw   = (float*)symaddr(g_tw);
    int*   te   = (int*)symaddr(g_te);
    int*   cnts = (int*)symaddr(g_counts);
    int*   offs = (int*)symaddr(g_offsets);
    int*   cur  = (int*)symaddr(g_cursor);
    int*   btok = (int*)symaddr(g_btok);
    int*   ppos = (int*)symaddr(g_ppos);
    float* gu   = (float*)symaddr(g_gu);
    float* act  = (float*)symaddr(g_act);
    float* ybuf = (float*)symaddr(g_ybuf);

    const float scale = 0.08838834764831843f;   // 1/sqrt(128)

    const size_t smem128  = (size_t)(3 * 128 * ASTRIDE + 3 * (BK * (128 + 8))) * 4;
    const size_t smem256  = (size_t)(3 * 128 * ASTRIDE + 3 * (BK * (256 + 8))) * 4;
    const size_t smemFA   = (size_t)(FBR*QSTR + FBC*KSTR + FBC*VSTR + FBR*PSTR
                                     + 8*FBR + 2*FBR) * 4;   // 200704 B
    static int attrDone = 0;
    if (!attrDone) {
        cudaFuncSetAttribute((const void*)gemm_tc<128,0>,
                             cudaFuncAttributeMaxDynamicSharedMemorySize, 120 * 1024);
        cudaFuncSetAttribute((const void*)gemm_tc<256,0>,
                             cudaFuncAttributeMaxDynamicSharedMemorySize, 164 * 1024);
        cudaFuncSetAttribute((const void*)flash_kernel,
                             cudaFuncAttributeMaxDynamicSharedMemorySize, 208 * 1024);
        attrDone = 1;
    }

    zero32_kernel<<<1, 32>>>(cnts, cur);

    // ---- attention ----
    rmsnorm_kernel<<<SQ, 256>>>(x, ln1, h1, HDM);

    // fused QKV projection: BN=256, grid (1,8,20)
    gemm_tc<256,0><<<dim3(1, 8, 20), 256, smem256>>>(h1, Wq, q, nullptr,
        SQ, HDM, HDM, 0, 0, 0, 0, 0, 1, 0, 0, 1.f, 3,
        nullptr, nullptr, nullptr, Wk, k, Wv, v);

    qknorm_rope_kernel<<<dim3(NHQ + NKVH, SQ), 128>>>(q, k, qnw, knw);

    // flash attention (scores + softmax + AV fused)
    flash_kernel<<<dim3(SQ/FBR, NHQ), 256, smemFA>>>(q, k, v, attn, scale);

    // h = x + attn @ Wo   (residual fused)
    gemm_tc<128,0><<<dim3(16, 8, 1), 256, smem128>>>(attn, Wo, h, x,
        SQ, NHQ*HDHD, NHQ*HDHD, HDM, HDM,
        0, 0, 0, 1, 0, 0, 1.f, 0,
        nullptr, nullptr, nullptr, nullptr, nullptr, nullptr, nullptr);

    // ---- MoE ----
    rmsnorm_kernel<<<SQ, 256>>>(h, ln2, h2, HDM);

    gemm_simt_kernel<<<dim3(1, 16, 1), 256>>>(h2, Wg, lg, SQ, NE, HDM, HDM, NE, NE);
    topk_kernel<<<4, 256>>>(lg, tw, te);
    count_kernel<<<(NPAIR + 255) / 256, 256>>>(te, cnts);
    scan_kernel<<<1, 32>>>(cnts, offs);
    assign_kernel<<<(NPAIR + 255) / 256, 256>>>(te, offs, cur, btok, ppos);

    // MoE up/gate: BN=256
    gemm_tc<256,0><<<dim3(2*IDIM/256, 8, NE), 256, smem256>>>(h2, Wgu, gu, nullptr,
        SQ, HDM, HDM, 2*IDIM, 2*IDIM,
        0, (long long)HDM*2*IDIM, 0, 1, 0, 0, 1.f, 1,
        cnts, offs, btok, nullptr, nullptr, nullptr, nullptr);

    silu_kernel<<<(int)(((long long)NPAIR*IDIM + 255) / 256), 256>>>(gu, act);

    // MoE down: BN=256
    gemm_tc<256,0><<<dim3(HDM/256, 8, NE), 256, smem256>>>(act, Wd, ybuf, nullptr,
        SQ, IDIM, IDIM, HDM, HDM,
        0, (long long)IDIM*HDM, 0, 1, 0, 0, 1.f, 2,
        cnts, offs, nullptr, nullptr, nullptr, nullptr, nullptr);

    combine_kernel<<<SQ, 256>>>(h, ybuf, ppos, tw, out);
}

// round 15
// speedup vs baseline: 1.4372x; 1.0323x over previous
#include <cuda_runtime.h>
#include <math.h>
#include <stdint.h>

// ---------------- problem constants ----------------
#define SQ   1024
#define HDM  2048
#define NHQ  32
#define NKVH 4
#define HDHD 128
#define NE   32
#define TOPK 8
#define IDIM 768
#define NPAIR (SQ*TOPK)   // 8192

// ---------------- device scratch ----------------
__device__ float g_h1[SQ*HDM];
__device__ float g_q [SQ*NHQ*HDHD];
__device__ float g_k [SQ*NKVH*HDHD];
__device__ float g_v [SQ*NKVH*HDHD];
__device__ float g_attn[SQ*NHQ*HDHD];
__device__ float g_h [SQ*HDM];
__device__ float g_h2[SQ*HDM];
__device__ float g_logits[SQ*NE];
__device__ float g_tw[NPAIR];
__device__ int   g_te[NPAIR];
__device__ int   g_counts[NE];
__device__ int   g_offsets[NE];
__device__ int   g_cursor[NE];
__device__ int   g_btok[NPAIR];
__device__ int   g_ppos[NPAIR];
__device__ float g_act[(long long)NPAIR*IDIM];
__device__ float g_ybuf[(long long)NPAIR*HDM];

// ---------------- helpers ----------------
__device__ __forceinline__ void cpasync16(void* dst, const void* src, int srcsize) {
    uint32_t d = (uint32_t)__cvta_generic_to_shared(dst);
    asm volatile("cp.async.cg.shared.global [%0], [%1], 16, %2;"
                 :: "r"(d), "l"(src), "r"(srcsize) : "memory");
}
__device__ __forceinline__ void cpasync_commit() {
    asm volatile("cp.async.commit_group;" ::: "memory");
}
// round-to-nearest-away into tf32's 19 kept bits (mma ignores low 13 bits)
__device__ __forceinline__ uint32_t rnd(float v) {
    return __float_as_uint(v) + 0x1000u;
}
#define MMA_TF32(acc, a, b) \
    asm volatile( \
        "mma.sync.aligned.m16n8k8.row.col.f32.tf32.tf32.f32 " \
        "{%0,%1,%2,%3}, {%4,%5,%6,%7}, {%8,%9}, {%0,%1,%2,%3};" \
        : "+f"((acc)[0]), "+f"((acc)[1]), "+f"((acc)[2]), "+f"((acc)[3]) \
        : "r"((a)[0]), "r"((a)[1]), "r"((a)[2]), "r"((a)[3]), \
          "r"((b)[0]), "r"((b)[1]))

// ---------------- small kernels ----------------
__global__ void zero32_kernel(int* counts, int* cursor) {
    int i = threadIdx.x;
    if (i < NE) { counts[i] = 0; cursor[i] = 0; }
}

__global__ void rmsnorm_kernel(const float* __restrict__ x, const float* __restrict__ w,
                               float* __restrict__ o, int ncols) {
    int row = blockIdx.x;
    const float* xr = x + (long long)row * ncols;
    float* orow = o + (long long)row * ncols;
    __shared__ float red[256];
    float s = 0.f;
    for (int c = threadIdx.x; c < ncols; c += 256) { float t = xr[c]; s += t * t; }
    red[threadIdx.x] = s; __syncthreads();
    for (int st = 128; st > 0; st >>= 1) {
        if (threadIdx.x < st) red[threadIdx.x] += red[threadIdx.x + st];
        __syncthreads();
    }
    float rms = rsqrtf(red[0] / (float)ncols + 1e-6f);
    for (int c = threadIdx.x; c < ncols; c += 256) orow[c] = xr[c] * rms * w[c];
}

__global__ void qknorm_rope_kernel(float* __restrict__ q, float* __restrict__ k,
                                   const float* __restrict__ qw, const float* __restrict__ kw) {
    int slot = blockIdx.x;
    int t    = blockIdx.y;
    float* vec; const float* w;
    if (slot < NHQ) { vec = q + (long long)t * (NHQ*HDHD) + slot * HDHD; w = qw; }
    else            { vec = k + (long long)t * (NKVH*HDHD) + (slot - NHQ) * HDHD; w = kw; }
    int d = threadIdx.x;
    float v = vec[d];
    float s = v * v;
    #pragma unroll
    for (int o = 16; o > 0; o >>= 1) s += __shfl_xor_sync(0xffffffffu, s, o);
    __shared__ float red[4];
    if ((d & 31) == 0) red[d >> 5] = s;
    __syncthreads();
    float tot = red[0] + red[1] + red[2] + red[3];
    float rms = rsqrtf(tot / 128.f + 1e-6f);
    float nv = v * rms * w[d];
    __shared__ float sv[128];
    sv[d] = nv;
    __syncthreads();
    int d2 = d & 63;
    float angle = (float)t * powf(10000.0f, -(float)(2 * d2) / 128.0f);
    float c = cosf(angle), sn = sinf(angle);
    float other = (d < 64) ? -sv[d + 64] : sv[d - 64];
    vec[d] = nv * c + other * sn;
}

// ---------------- flash attention: scores+softmax+AV fused ----------------
#define FBR 128
#define FBC 64
#define QSTR 164
#define KSTR 164
#define VSTR 136
#define PSTR 68
__global__ void __launch_bounds__(256, 1)
flash_kernel(const float* __restrict__ q, const float* __restrict__ k,
             const float* __restrict__ v, float* __restrict__ attn, float scale) {
    int rb = blockIdx.x;
    int h  = blockIdx.y;
    int kv = h >> 3;
    int tid = threadIdx.x;
    int warp = tid >> 5, lane = tid & 31;
    int g = lane >> 2, t = lane & 3;
    int wr  = (warp >> 2) * 64;
    int wcS = (warp & 3) * 16;
    int wcO = (warp & 3) * 32;
    int wq  = warp & 3;

    extern __shared__ float sm[];
    float* Qs   = sm;
    float* Ks   = Qs + FBR*QSTR;
    float* Vs   = Ks + FBC*KSTR;
    float* Ps   = Vs + FBC*VSTR;
    float* redm = Ps + FBR*PSTR;
    float* redl = redm + 4*FBR;
    float* m_s  = redl + 4*FBR;
    float* l_s  = m_s + FBR;

    int row0 = rb * FBR;

    for (int i = tid; i < FBR; i += 256) { m_s[i] = -1e30f; l_s[i] = 0.f; }

    for (int i = tid; i < FBR * 32; i += 256) {
        int r = i >> 5, cq = i & 31;
        cpasync16(Qs + r*QSTR + cq*4,
                  q + (long long)(row0 + r)*(NHQ*HDHD) + h*HDHD + cq*4, 16);
    }
    for (int i = tid; i < FBC * 32; i += 256) {
        int n = i >> 5, cq = i & 31;
        cpasync16(Ks + n*KSTR + cq*4,
                  k + (long long)n*(NKVH*HDHD) + kv*HDHD + cq*4, 16);
        cpasync16(Vs + n*VSTR + cq*4,
                  v + (long long)n*(NKVH*HDHD) + kv*HDHD + cq*4, 16);
    }
    cpasync_commit();

    float accO[4][4][4];
    #pragma unroll
    for (int i1 = 0; i1 < 4; i1++)
        #pragma unroll
        for (int i2 = 0; i2 < 4; i2++)
            #pragma unroll
            for (int i3 = 0; i3 < 4; i3++) accO[i1][i2][i3] = 0.f;

    int jmax = 2*rb + 1;

    for (int j = 0; j <= jmax; j++) {
        asm volatile("cp.async.wait_group 0;" ::: "memory");
        __syncthreads();

        // ---- S = Q @ K_j^T ----
        float accS[4][2][4];
        #pragma unroll
        for (int i1 = 0; i1 < 4; i1++)
            #pragma unroll
            for (int i2 = 0; i2 < 2; i2++)
                #pragma unroll
                for (int i3 = 0; i3 < 4; i3++) accS[i1][i2][i3] = 0.f;
        #pragma unroll
        for (int ks = 0; ks < 16; ks++) {
            int kb = ks * 8;
            uint32_t a[4][4], b[2][2];
            #pragma unroll
            for (int fm = 0; fm < 4; fm++) {
                int m0 = wr + fm * 16;
                a[fm][0] = rnd(Qs[(m0 + g    ) * QSTR + kb + t    ]);
                a[fm][1] = rnd(Qs[(m0 + g + 8) * QSTR + kb + t    ]);
                a[fm][2] = rnd(Qs[(m0 + g    ) * QSTR + kb + t + 4]);
                a[fm][3] = rnd(Qs[(m0 + g + 8) * QSTR + kb + t + 4]);
            }
            #pragma unroll
            for (int fn = 0; fn < 2; fn++) {
                int n0 = wcS + fn * 8 + g;
                b[fn][0] = rnd(Ks[n0 * KSTR + kb + t    ]);
                b[fn][1] = rnd(Ks[n0 * KSTR + kb + t + 4]);
            }
            #pragma unroll
            for (int fm = 0; fm < 4; fm++)
                #pragma unroll
                for (int fn = 0; fn < 2; fn++)
                    MMA_TF32(accS[fm][fn], a[fm], b[fn]);
        }

        // scale + causal mask + per-row max
        int colbase = j * FBC + wcS;
        #pragma unroll
        for (int fm = 0; fm < 4; fm++)
            #pragma unroll
            for (int rr = 0; rr < 2; rr++) {
                int row = row0 + wr + fm*16 + g + rr*8;
                float mx = -1e30f;
                #pragma unroll
                for (int fn = 0; fn < 2; fn++)
                    #pragma unroll
                    for (int cc = 0; cc < 2; cc++) {
                        float sv = accS[fm][fn][rr*2 + cc] * scale;
                        int col = colbase + fn*8 + t*2 + cc;
                        if (col > row) sv = -1e30f;
                        accS[fm][fn][rr*2 + cc] = sv;
                        mx = fmaxf(mx, sv);
                    }
                mx = fmaxf(mx, __shfl_xor_sync(0xffffffffu, mx, 1));
                mx = fmaxf(mx, __shfl_xor_sync(0xffffffffu, mx, 2));
                if (t == 0) redm[wq*FBR + wr + fm*16 + g + rr*8] = mx;
            }
        __syncthreads();

        if (j < jmax) {
            for (int i = tid; i < FBC * 32; i += 256) {
                int n = i >> 5, cq = i & 31;
                cpasync16(Ks + n*KSTR + cq*4,
                          k + (long long)((j+1)*FBC + n)*(NKVH*HDHD) + kv*HDHD + cq*4, 16);
            }
        }
        cpasync_commit();

        float mnew[4][2], esr[4][2];
        #pragma unroll
        for (int fm = 0; fm < 4; fm++)
            #pragma unroll
            for (int rr = 0; rr < 2; rr++) {
                int row = wr + fm*16 + g + rr*8;
                float mo = m_s[row];
                float mn = fmaxf(fmaxf(redm[row], redm[FBR + row]),
                                 fmaxf(redm[2*FBR + row], redm[3*FBR + row]));
                mn = fmaxf(mn, mo);
                mnew[fm][rr] = mn;
                esr[fm][rr] = __expf(mo - mn);
            }
        #pragma unroll
        for (int fm = 0; fm < 4; fm++)
            #pragma unroll
            for (int rr = 0; rr < 2; rr++) {
                int row = wr + fm*16 + g + rr*8;
                float lsum = 0.f;
                #pragma unroll
                for (int fn = 0; fn < 2; fn++)
                    #pragma unroll
                    for (int cc = 0; cc < 2; cc++) {
                        float p = __expf(accS[fm][fn][rr*2 + cc] - mnew[fm][rr]);
                        lsum += p;
                        Ps[row * PSTR + wcS + fn*8 + t*2 + cc] = p;
                    }
                lsum += __shfl_xor_sync(0xffffffffu, lsum, 1);
                lsum += __shfl_xor_sync(0xffffffffu, lsum, 2);
                if (t == 0) redl[wq*FBR + row] = lsum;
            }
        #pragma unroll
        for (int fm = 0; fm < 4; fm++)
            #pragma unroll
            for (int fn = 0; fn < 4; fn++)
                #pragma unroll
                for (int r = 0; r < 4; r++)
                    accO[fm][fn][r] *= esr[fm][r >> 1];
        __syncthreads();

        if (wq == 0 && t == 0) {
            #pragma unroll
            for (int fm = 0; fm < 4; fm++)
                #pragma unroll
                for (int rr = 0; rr < 2; rr++) {
                    int row = wr + fm*16 + g + rr*8;
                    l_s[row] = l_s[row] * esr[fm][rr]
                             + redl[row] + redl[FBR + row]
                             + redl[2*FBR + row] + redl[3*FBR + row];
                    m_s[row] = mnew[fm][rr];
                }
        }

        // ---- O += P @ V ----
        #pragma unroll
        for (int ks = 0; ks < 8; ks++) {
            int kb = ks * 8;
            uint32_t a[4][4], b[4][2];
            #pragma unroll
            for (int fm = 0; fm < 4; fm++) {
                int m0 = wr + fm * 16;
                a[fm][0] = rnd(Ps[(m0 + g    ) * PSTR + kb + t    ]);
                a[fm][1] = rnd(Ps[(m0 + g + 8) * PSTR + kb + t    ]);
                a[fm][2] = rnd(Ps[(m0 + g    ) * PSTR + kb + t + 4]);
                a[fm][3] = rnd(Ps[(m0 + g + 8) * PSTR + kb + t + 4]);
            }
            #pragma unroll
            for (int fn = 0; fn < 4; fn++) {
                int n0 = wcO + fn * 8 + g;
                b[fn][0] = rnd(Vs[(kb + t    ) * VSTR + n0]);
                b[fn][1] = rnd(Vs[(kb + t + 4) * VSTR + n0]);
            }
            #pragma unroll
            for (int fm = 0; fm < 4; fm++)
                #pragma unroll
                for (int fn = 0; fn < 4; fn++)
                    MMA_TF32(accO[fm][fn], a[fm], b[fn]);
        }
        __syncthreads();

        if (j < jmax) {
            for (int i = tid; i < FBC * 32; i += 256) {
                int n = i >> 5, cq = i & 31;
                cpasync16(Vs + n*VSTR + cq*4,
                          v + (long long)((j+1)*FBC + n)*(NKVH*HDHD) + kv*HDHD + cq*4, 16);
            }
        }
        cpasync_commit();
    }

    __syncthreads();
    #pragma unroll
    for (int fm = 0; fm < 4; fm++)
        #pragma unroll
        for (int rr = 0; rr < 2; rr++) {
            int row = wr + fm*16 + g + rr*8;
            float inv = 1.f / l_s[row];
            float* op = attn + (long long)(row0 + row)*(NHQ*HDHD) + h*HDHD;
            #pragma unroll
            for (int fn = 0; fn < 4; fn++) {
                int c = wcO + fn*8 + t*2;
                op[c]     = accO[fm][fn][rr*2    ] * inv;
                op[c + 1] = accO[fm][fn][rr*2 + 1] * inv;
            }
        }
}

__global__ void topk_kernel(const float* __restrict__ logits, float* __restrict__ tw,
                            int* __restrict__ te) {
    int t = blockIdx.x * blockDim.x + threadIdx.x;
    if (t >= SQ) return;
    float p[NE];
    float m = -1e30f;
    for (int e = 0; e < NE; e++) { p[e] = logits[t * NE + e]; m = fmaxf(m, p[e]); }
    float s = 0.f;
    for (int e = 0; e < NE; e++) { p[e] = expf(p[e] - m); s += p[e]; }
    float inv = 1.f / s;
    bool used[NE];
    for (int e = 0; e < NE; e++) used[e] = false;
    for (int kk = 0; kk < TOPK; kk++) {
        int best = -1; float bv = -1e30f;
        for (int e = 0; e < NE; e++)
            if (!used[e] && p[e] > bv) { bv = p[e]; best = e; }
        used[best] = true;
        te[t * TOPK + kk] = best;
        tw[t * TOPK + kk] = p[best] * inv;
    }
}

__global__ void count_kernel(const int* __restrict__ te, int* __restrict__ counts) {
    int p = blockIdx.x * 256 + threadIdx.x;
    if (p < NPAIR) atomicAdd(&counts[te[p]], 1);
}

__global__ void scan_kernel(const int* __restrict__ counts, int* __restrict__ offsets) {
    if (threadIdx.x == 0) {
        int s = 0;
        for (int e = 0; e < NE; e++) { offsets[e] = s; s += counts[e]; }
    }
}

__global__ void assign_kernel(const int* __restrict__ te, const int* __restrict__ offsets,
                              int* __restrict__ cursor, int* __restrict__ btok,
                              int* __restrict__ ppos) {
    int p = blockIdx.x * 256 + threadIdx.x;
    if (p >= NPAIR) return;
    int e = te[p];
    int pos = offsets[e] + atomicAdd(&cursor[e], 1);
    btok[pos] = p >> 3;
    ppos[p] = pos;
}

__global__ void combine_kernel(const float* __restrict__ h, const float* __restrict__ ybuf,
                               const int* __restrict__ ppos, const float* __restrict__ tw,
                               float* __restrict__ out) {
    int t = blockIdx.x;
    __shared__ int   pos[TOPK];
    __shared__ float ww[TOPK];
    if (threadIdx.x < TOPK) {
        pos[threadIdx.x] = ppos[t * TOPK + threadIdx.x];
        ww[threadIdx.x]  = tw[t * TOPK + threadIdx.x];
    }
    __syncthreads();
    const float4* h4 = (const float4*)(h + (long long)t * HDM);
    float4* o4 = (float4*)(out + (long long)t * HDM);
    for (int c = threadIdx.x; c < HDM / 4; c += 256) {
        float4 a = h4[c];
        #pragma unroll
        for (int kk = 0; kk < TOPK; kk++) {
            float4 b = ((const float4*)(ybuf + (long long)pos[kk] * HDM))[c];
            float wv = ww[kk];
            a.x += wv * b.x; a.y += wv * b.y; a.z += wv * b.z; a.w += wv * b.w;
        }
        o4[c] = a;
    }
}

// ---------------- exact fp32 SIMT GEMM (gate logits only) ----------------
__global__ void gemm_simt_kernel(const float* __restrict__ A, const float* __restrict__ B,
                                 float* __restrict__ C, int M, int N, int K,
                                 int lda, int ldb, int ldc) {
    __shared__ float As[16][64 + 4];
    __shared__ float Bs[16][64];
    int tid = threadIdx.x;
    int tx = tid & 15, ty = tid >> 4;
    int row0 = blockIdx.y * 64;
    int col0 = blockIdx.x * 64;
    float acc[4][4] = {};
    for (int k0 = 0; k0 < K; k0 += 16) {
        for (int i = tid; i < 64 * 16; i += 256) {
            int m = i >> 4, kk = i & 15;
            int gr = row0 + m;
            As[kk][m] = (gr < M) ? A[(long long)gr * lda + k0 + kk] : 0.f;
        }
        for (int i = tid; i < 16 * 64; i += 256) {
            int kk = i >> 6, n = i & 63;
            int gc = col0 + n;
            Bs[kk][n] = (gc < N) ? B[(long long)(k0 + kk) * ldb + gc] : 0.f;
        }
        __syncthreads();
        #pragma unroll
        for (int kk = 0; kk < 16; kk++) {
            float a[4], b[4];
            #pragma unroll
            for (int i = 0; i < 4; i++) a[i] = As[kk][ty * 4 + i];
            #pragma unroll
            for (int j = 0; j < 4; j++) b[j] = Bs[kk][tx * 4 + j];
            #pragma unroll
            for (int i = 0; i < 4; i++)
                #pragma unroll
                for (int j = 0; j < 4; j++)
                    acc[i][j] += a[i] * b[j];
        }
        __syncthreads();
    }
    #pragma unroll
    for (int i = 0; i < 4; i++) {
        int r = row0 + ty * 4 + i;
        if (r >= M) continue;
        #pragma unroll
        for (int j = 0; j < 4; j++) {
            int c = col0 + tx * 4 + j;
            if (c < N) C[(long long)r * ldc + c] = acc[i][j];
        }
    }
}

// ---------------- tf32 tensor-core GEMM, BK=32, 3-stage cp.async ----------------
#define BK 32
#define ASTRIDE 36
template<int BN, int TRANSB>
__global__ void __launch_bounds__(256, 1)
gemm_tc(const float* __restrict__ A, const float* __restrict__ B, float* __restrict__ C,
        const float* __restrict__ resid,
        int M, int K, int lda, int ldb, int ldc,
        long long sA, long long sB, long long sC, int bDivB,
        int causal, int trimK, float alpha, int mode,
        const int* __restrict__ counts, const int* __restrict__ offsets,
        const int* __restrict__ btok,
        const float* __restrict__ B2, float* __restrict__ C2,
        const float* __restrict__ B3, float* __restrict__ C3) {
    constexpr int BM = 128;
    constexpr int THREADS = 256;
    constexpr int WN = BN / 4;
    constexpr int FM = 4, FN = WN / 8;
    constexpr int ASZ = BM * ASTRIDE;
    constexpr int BSZ = TRANSB ? (BN * ASTRIDE) : (BK * (BN + 8));

    extern __shared__ float smem[];
    float* sA_ = smem;
    float* sB_ = smem + 3 * ASZ;
    __shared__ int stok[BM];

    int z = blockIdx.z;
    int tid = threadIdx.x;
    int row0 = blockIdx.y * BM;
    int col0 = blockIdx.x * BN;

    const float* Az = A;
    const float* Bz;
    float* Cz;
    if (mode == 0) {
        Az = A + (long long)z * sA;
        Bz = B + (long long)(z / bDivB) * sB;
        Cz = C + (long long)z * sC;
    } else if (mode == 3) {
        if (z < 16)      { Bz = B;  Cz = C;  ldb = ldc = NHQ*HDHD;  col0 = z * BN; }
        else if (z < 18) { Bz = B2; Cz = C2; ldb = ldc = NKVH*HDHD; col0 = (z - 16) * BN; }
        else             { Bz = B3; Cz = C3; ldb = ldc = NKVH*HDHD; col0 = (z - 18) * BN; }
    } else {
        Bz = B + (long long)z * sB;
        Cz = C;
    }

    int cnt = M, start = 0;
    if (mode == 1 || mode == 2) { cnt = counts[z]; start = offsets[z]; }
    if ((mode == 1 || mode == 2) && row0 >= cnt) return;
    if (causal && col0 > row0) return;

    if (mode == 1) {
        for (int i = tid; i < BM; i += THREADS)
            stok[i] = (row0 + i < cnt) ? btok[start + row0 + i] : 0;
        __syncthreads();
    }

    int warp = tid >> 5, lane = tid & 31;
    int wr = (warp >> 2) * 64, wc = (warp & 3) * WN;
    int g = lane >> 2, t = lane & 3;

    float acc[FM][FN][4];
    #pragma unroll
    for (int i = 0; i < FM; i++)
        #pragma unroll
        for (int j = 0; j < FN; j++)
            #pragma unroll
            for (int r = 0; r < 4; r++) acc[i][j][r] = 0.f;

    auto loadTiles = [&](int st, int k0) {
        float* a = sA_ + st * ASZ;
        float* b = sB_ + st * BSZ;
        #pragma unroll
        for (int i = tid; i < BM * 8; i += THREADS) {
            int r = i >> 3, kq = i & 7;
            bool val = (row0 + r < cnt);
            long long ar = 0;
            if (val) {
                if (mode == 1)      ar = stok[r];
                else if (mode == 2) ar = start + row0 + r;
                else                ar = row0 + r;
            }
            cpasync16(a + r * ASTRIDE + kq * 4, Az + ar * lda + k0 + kq * 4, val ? 16 : 0);
        }
        if (!TRANSB) {
            #pragma unroll
            for (int i = tid; i < BK * (BN / 4); i += THREADS) {
                int kk = i / (BN / 4), nq = i % (BN / 4);
                cpasync16(b + kk * (BN + 8) + nq * 4,
                          Bz + (long long)(k0 + kk) * ldb + col0 + nq * 4, 16);
            }
        } else {
            #pragma unroll
            for (int i = tid; i < BN * 8; i += THREADS) {
                int n = i >> 3, kq = i & 7;
                cpasync16(b + n * ASTRIDE + kq * 4,
                          Bz + (long long)(col0 + n) * ldb + k0 + kq * 4, 16);
            }
        }
    };

    auto compute = [&](int st) {
        const float* a_ = sA_ + st * ASZ;
        const float* b_ = sB_ + st * BSZ;
        #pragma unroll
        for (int ks = 0; ks < 4; ks++) {
            int kb = ks * 8;
            uint32_t a[FM][4], b[FN][2];
            #pragma unroll
            for (int fm = 0; fm < FM; fm++) {
                int m0 = wr + fm * 16;
                a[fm][0] = rnd(a_[(m0 + g) * ASTRIDE + kb + t]);
                a[fm][1] = rnd(a_[(m0 + g + 8) * ASTRIDE + kb + t]);
                a[fm][2] = rnd(a_[(m0 + g) * ASTRIDE + kb + t + 4]);
                a[fm][3] = rnd(a_[(m0 + g + 8) * ASTRIDE + kb + t + 4]);
            }
            #pragma unroll
            for (int fn = 0; fn < FN; fn++) {
                int n0 = wc + fn * 8 + g;
                if (TRANSB) {
                    b[fn][0] = rnd(b_[n0 * ASTRIDE + kb + t]);
                    b[fn][1] = rnd(b_[n0 * ASTRIDE + kb + t + 4]);
                } else {
                    b[fn][0] = rnd(b_[(kb + t) * (BN + 8) + n0]);
                    b[fn][1] = rnd(b_[(kb + t + 4) * (BN + 8) + n0]);
                }
            }
            #pragma unroll
            for (int fm = 0; fm < FM; fm++)
                #pragma unroll
                for (int fn = 0; fn < FN; fn++)
                    MMA_TF32(acc[fm][fn], a[fm], b[fn]);
        }
    };

    int kLimit = trimK ? (row0 + BM < K ? row0 + BM : K) : K;
    int nk = kLimit / BK;

    loadTiles(0, 0);      cpasync_commit();
    loadTiles(1, BK);     cpasync_commit();
    for (int ks = 0; ks < nk; ks++) {
        asm volatile("cp.async.wait_group 1;" ::: "memory");
        __syncthreads();
        if (ks + 2 < nk) loadTiles((ks + 2) % 3, (ks + 2) * BK);
        cpasync_commit();
        compute(ks % 3);
    }

    // ---- epilogue ----
    #pragma unroll
    for (int fm = 0; fm < FM; fm++) {
        #pragma unroll
        for (int rr = 0; rr < 2; rr++) {
            int lr = wr + fm * 16 + g + rr * 8;
            if (row0 + lr >= cnt) continue;
            long long crow = (mode == 1 || mode == 2) ? (long long)(start + row0 + lr)
                                                      : (long long)(row0 + lr);
            float* cp = Cz + crow * ldc;
            const float* rp = resid ? (resid + (long long)(row0 + lr) * ldc) : nullptr;
            #pragma unroll
            for (int fn = 0; fn < FN; fn++) {
                int c = col0 + wc + fn * 8 + t * 2;
                float v0 = alpha * acc[fm][fn][rr * 2 + 0];
                float v1 = alpha * acc[fm][fn][rr * 2 + 1];
                if (rp) { v0 += rp[c]; v1 += rp[c + 1]; }
                cp[c] = v0;
                cp[c + 1] = v1;
            }
        }
    }
}

// ---------------- MoE up GEMM with fused SiLU: act = silu(h2@Wg) * (h2@Wu) ----------------
// Each CTA: 128 gathered rows x (128 gate cols + matching 128 up cols).
// Warp owns 32 gate cols (fn 0-3) + the same 32 up cols (fn 4-7); epilogue pairs them.
__global__ void __launch_bounds__(256, 1)
moe_up_fused(const float* __restrict__ h2, const float* __restrict__ Wgu,
             float* __restrict__ act,
             const int* __restrict__ counts, const int* __restrict__ offsets,
             const int* __restrict__ btok) {
    constexpr int BM = 128;
    constexpr int ASZ = BM * ASTRIDE;
    constexpr int BSZ = BK * (256 + 8);

    extern __shared__ float smem[];
    float* sA_ = smem;
    float* sB_ = smem + 3 * ASZ;
    __shared__ int stok[BM];

    int e = blockIdx.z;
    int tid = threadIdx.x;
    int row0 = blockIdx.y * BM;
    int col0 = blockIdx.x * 128;          // gate column base (0..IDIM)

    int cnt = counts[e], start = offsets[e];
    if (row0 >= cnt) return;

    const float* Bz = Wgu + (long long)e * (HDM * 2 * IDIM);

    for (int i = tid; i < BM; i += 256)
        stok[i] = (row0 + i < cnt) ? btok[start + row0 + i] : 0;
    __syncthreads();

    int warp = tid >> 5, lane = tid & 31;
    int wr = (warp >> 2) * 64, wcg = (warp & 3) * 32;
    int g = lane >> 2, t = lane & 3;

    float acc[4][8][4];
    #pragma unroll
    for (int i = 0; i < 4; i++)
        #pragma unroll
        for (int j = 0; j < 8; j++)
            #pragma unroll
            for (int r = 0; r < 4; r++) acc[i][j][r] = 0.f;

    auto loadTiles = [&](int st, int k0) {
        float* a = sA_ + st * ASZ;
        float* b = sB_ + st * BSZ;
        #pragma unroll
        for (int i = tid; i < BM * 8; i += 256) {
            int r = i >> 3, kq = i & 7;
            bool val = (row0 + r < cnt);
            long long ar = val ? stok[r] : 0;
            cpasync16(a + r * ASTRIDE + kq * 4, h2 + ar * HDM + k0 + kq * 4, val ? 16 : 0);
        }
        // B: smem cols [0,128) = gate cols col0+., [128,256) = up cols IDIM+col0+.
        #pragma unroll
        for (int i = tid; i < BK * 64; i += 256) {
            int kk = i >> 6, nq = i & 63;
            int gc = (nq < 32) ? (col0 + nq * 4) : (IDIM + col0 + (nq - 32) * 4);
            cpasync16(b + kk * 264 + nq * 4,
                      Bz + (long long)(k0 + kk) * (2 * IDIM) + gc, 16);
        }
    };

    auto compute = [&](int st) {
        const float* a_ = sA_ + st * ASZ;
        const float* b_ = sB_ + st * BSZ;
        #pragma unroll
        for (int ks = 0; ks < 4; ks++) {
            int kb = ks * 8;
            uint32_t a[4][4], b[8][2];
            #pragma unroll
            for (int fm = 0; fm < 4; fm++) {
                int m0 = wr + fm * 16;
                a[fm][0] = rnd(a_[(m0 + g) * ASTRIDE + kb + t]);
                a[fm][1] = rnd(a_[(m0 + g + 8) * ASTRIDE + kb + t]);
                a[fm][2] = rnd(a_[(m0 + g) * ASTRIDE + kb + t + 4]);
                a[fm][3] = rnd(a_[(m0 + g + 8) * ASTRIDE + kb + t + 4]);
            }
            #pragma unroll
            for (int fn = 0; fn < 8; fn++) {
                int n0 = (fn < 4) ? (wcg + fn * 8 + g)
                                  : (128 + wcg + (fn - 4) * 8 + g);
                b[fn][0] = rnd(b_[(kb + t) * 264 + n0]);
                b[fn][1] = rnd(b_[(kb + t + 4) * 264 + n0]);
            }
            #pragma unroll
            for (int fm = 0; fm < 4; fm++)
                #pragma unroll
                for (int fn = 0; fn < 8; fn++)
                    MMA_TF32(acc[fm][fn], a[fm], b[fn]);
        }
    };

    int nk = HDM / BK;
    loadTiles(0, 0);      cpasync_commit();
    loadTiles(1, BK);     cpasync_commit();
    for (int ks = 0; ks < nk; ks++) {
        asm volatile("cp.async.wait_group 1;" ::: "memory");
        __syncthreads();
        if (ks + 2 < nk) loadTiles((ks + 2) % 3, (ks + 2) * BK);
        cpasync_commit();
        compute(ks % 3);
    }

    // ---- epilogue: act = silu(gate) * up ----
    #pragma unroll
    for (int fm = 0; fm < 4; fm++) {
        #pragma unroll
        for (int rr = 0; rr < 2; rr++) {
            int lr = wr + fm * 16 + g + rr * 8;
            if (row0 + lr >= cnt) continue;
            float* ap = act + (long long)(start + row0 + lr) * IDIM;
            #pragma unroll
            for (int fn = 0; fn < 4; fn++) {
                int c = col0 + wcg + fn * 8 + t * 2;
                #pragma unroll
                for (int cc = 0; cc < 2; cc++) {
                    float gv = acc[fm][fn][rr * 2 + cc];
                    float uv = acc[fm][fn + 4][rr * 2 + cc];
                    ap[c + cc] = (gv / (1.f + __expf(-gv))) * uv;
                }
            }
        }
    }
}

// ---------------- host launcher ----------------
static void* symaddr(const void* s) { void* p = nullptr; cudaGetSymbolAddress(&p, s); return p; }

extern "C" void kernel_launch(void* const* d_in, const int* in_sizes, int n_in,
                              void* d_out, int out_size) {
    const float* x   = (const float*)d_in[0];
    const float* ln1 = (const float*)d_in[1];
    const float* ln2 = (const float*)d_in[2];
    const float* qnw = (const float*)d_in[3];
    const float* knw = (const float*)d_in[4];
    const float* Wq  = (const float*)d_in[5];
    const float* Wk  = (const float*)d_in[6];
    const float* Wv  = (const float*)d_in[7];
    const float* Wo  = (const float*)d_in[8];
    const float* Wg  = (const float*)d_in[9];
    const float* Wgu = (const float*)d_in[10];
    const float* Wd  = (const float*)d_in[11];
    float* out = (float*)d_out;

    float* h1   = (float*)symaddr(g_h1);
    float* q    = (float*)symaddr(g_q);
    float* k    = (float*)symaddr(g_k);
    float* v    = (float*)symaddr(g_v);
    float* attn = (float*)symaddr(g_attn);
    float* h    = (float*)symaddr(g_h);
    float* h2   = (float*)symaddr(g_h2);
    float* lg   = (float*)symaddr(g_logits);
    float* tw   = (float*)symaddr(g_tw);
    int*   te   = (int*)symaddr(g_te);
    int*   cnts = (int*)symaddr(g_counts);
    int*   offs = (int*)symaddr(g_offsets);
    int*   cur  = (int*)symaddr(g_cursor);
    int*   btok = (int*)symaddr(g_btok);
    int*   ppos = (int*)symaddr(g_ppos);
    float* act  = (float*)symaddr(g_act);
    float* ybuf = (float*)symaddr(g_ybuf);

    const float scale = 0.08838834764831843f;   // 1/sqrt(128)

    const size_t smem128  = (size_t)(3 * 128 * ASTRIDE + 3 * (BK * (128 + 8))) * 4;
    const size_t smem256  = (size_t)(3 * 128 * ASTRIDE + 3 * (BK * (256 + 8))) * 4;
    const size_t smemFA   = (size_t)(FBR*QSTR + FBC*KSTR + FBC*VSTR + FBR*PSTR
                                     + 8*FBR + 2*FBR) * 4;
    static int attrDone = 0;
    if (!attrDone) {
        cudaFuncSetAttribute((const void*)gemm_tc<128,0>,
                             cudaFuncAttributeMaxDynamicSharedMemorySize, 120 * 1024);
        cudaFuncSetAttribute((const void*)gemm_tc<256,0>,
                             cudaFuncAttributeMaxDynamicSharedMemorySize, 164 * 1024);
        cudaFuncSetAttribute((const void*)moe_up_fused,
                             cudaFuncAttributeMaxDynamicSharedMemorySize, 164 * 1024);
        cudaFuncSetAttribute((const void*)flash_kernel,
                             cudaFuncAttributeMaxDynamicSharedMemorySize, 208 * 1024);
        attrDone = 1;
    }

    zero32_kernel<<<1, 32>>>(cnts, cur);

    // ---- attention ----
    rmsnorm_kernel<<<SQ, 256>>>(x, ln1, h1, HDM);

    // fused QKV projection: BN=256, grid (1,8,20)
    gemm_tc<256,0><<<dim3(1, 8, 20), 256, smem256>>>(h1, Wq, q, nullptr,
        SQ, HDM, HDM, 0, 0, 0, 0, 0, 1, 0, 0, 1.f, 3,
        nullptr, nullptr, nullptr, Wk, k, Wv, v);

    qknorm_rope_kernel<<<dim3(NHQ + NKVH, SQ), 128>>>(q, k, qnw, knw);

    // flash attention (scores + softmax + AV fused)
    flash_kernel<<<dim3(SQ/FBR, NHQ), 256, smemFA>>>(q, k, v, attn, scale);

    // h = x + attn @ Wo   (residual fused)
    gemm_tc<128,0><<<dim3(16, 8, 1), 256, smem128>>>(attn, Wo, h, x,
        SQ, NHQ*HDHD, NHQ*HDHD, HDM, HDM,
        0, 0, 0, 1, 0, 0, 1.f, 0,
        nullptr, nullptr, nullptr, nullptr, nullptr, nullptr, nullptr);

    // ---- MoE ----
    rmsnorm_kernel<<<SQ, 256>>>(h, ln2, h2, HDM);

    gemm_simt_kernel<<<dim3(1, 16, 1), 256>>>(h2, Wg, lg, SQ, NE, HDM, HDM, NE, NE);
    topk_kernel<<<4, 256>>>(lg, tw, te);
    count_kernel<<<(NPAIR + 255) / 256, 256>>>(te, cnts);
    scan_kernel<<<1, 32>>>(cnts, offs);
    assign_kernel<<<(NPAIR + 255) / 256, 256>>>(te, offs, cur, btok, ppos);

    // MoE up/gate + SiLU fused: grid (IDIM/128=6, 8, 32)
    moe_up_fused<<<dim3(IDIM/128, 8, NE), 256, smem256>>>(h2, Wgu, act, cnts, offs, btok);

    // MoE down: BN=256, grid (8,8,32)
    gemm_tc<256,0><<<dim3(HDM/256, 8, NE), 256, smem256>>>(act, Wd, ybuf, nullptr,
        SQ, IDIM, IDIM, HDM, HDM,
        0, (long long)IDIM*HDM, 0, 1, 0, 0, 1.f, 2,
        cnts, offs, nullptr, nullptr, nullptr, nullptr, nullptr);

    combine_kernel<<<SQ, 256>>>(h, ybuf, ppos, tw, out);
}